// round 4
// baseline (speedup 1.0000x reference)
#include <cuda_runtime.h>
#include <math.h>

#define D   256
#define NB  65536
#define NR  131072
#define CF  128
#define CR  512
#define INV_T (1.0f/0.3f)
#define EPSN  1e-12f

// ---------------- scratch (static device globals; no runtime alloc) ----------------
__device__ float g_invn_f[NB];
__device__ float g_invn_r[NR];
__device__ int   g_cnt_f[CF];
__device__ int   g_cnt_r[CR];
__device__ int   g_off_f[CF];
__device__ int   g_off_r[CR];
__device__ int   g_cur_f[CF];
__device__ int   g_cur_r[CR];
__device__ int   g_srt_f[NB];
__device__ int   g_srt_r[NR];
__device__ float g_sum_f[CF*D];
__device__ float g_sum_r[CR*D];
__device__ float g_pro_f[CF*D];
__device__ float g_pro_r[CR*D];
__device__ float g_ls_f[NB/128];
__device__ float g_lc_f[NB/128];
__device__ float g_ls_r[NR/128];
__device__ float g_lc_r[NR/128];

// ---------------- f32x2 packed-FMA helpers ----------------
__device__ __forceinline__ unsigned long long pack2(float x, float y) {
    unsigned long long r;
    asm("mov.b64 %0, {%1, %2};" : "=l"(r) : "f"(x), "f"(y));
    return r;
}
__device__ __forceinline__ void fma2(unsigned long long& d, unsigned long long a, unsigned long long b) {
    asm("fma.rn.f32x2 %0, %1, %2, %0;" : "+l"(d) : "l"(a), "l"(b));
}
__device__ __forceinline__ float2 unpack2(unsigned long long v) {
    float2 f;
    asm("mov.b64 {%0, %1}, %2;" : "=f"(f.x), "=f"(f.y) : "l"(v));
    return f;
}

// ---------------- zero per-call counters ----------------
__global__ void k_zero() {
    int t = threadIdx.x;
    if (t < CF) g_cnt_f[t] = 0;
    if (t < CR) g_cnt_r[t] = 0;
}

// ---------------- row inverse norms: one warp per row ----------------
__global__ void k_norm(const float* __restrict__ x, float* __restrict__ invn) {
    int row  = blockIdx.x * 8 + (threadIdx.x >> 5);
    int lane = threadIdx.x & 31;
    const float4* p = (const float4*)(x + (size_t)row * D);
    float4 a = p[lane];
    float4 b = p[lane + 32];
    float ss = a.x*a.x + a.y*a.y + a.z*a.z + a.w*a.w
             + b.x*b.x + b.y*b.y + b.z*b.z + b.w*b.w;
    #pragma unroll
    for (int o = 16; o; o >>= 1) ss += __shfl_xor_sync(0xffffffffu, ss, o);
    if (lane == 0) invn[row] = 1.0f / fmaxf(sqrtf(ss), EPSN);
}

// ---------------- label histogram (smem-aggregated) ----------------
__global__ void k_hist(const int* __restrict__ lab, int n, int* __restrict__ cnt, int C) {
    __shared__ int sh[CR];
    for (int i = threadIdx.x; i < C; i += blockDim.x) sh[i] = 0;
    __syncthreads();
    for (int i = blockIdx.x * blockDim.x + threadIdx.x; i < n; i += gridDim.x * blockDim.x) {
        int l = lab[i];
        if (l >= 0) atomicAdd(&sh[l], 1);
    }
    __syncthreads();
    for (int i = threadIdx.x; i < C; i += blockDim.x)
        if (sh[i]) atomicAdd(&cnt[i], sh[i]);
}

// ---------------- exclusive scan of counts -> offsets + cursors (1 block) ----------------
__global__ void k_scan() {
    __shared__ int sh[CR];
    int t = threadIdx.x;
    // fti
    if (t < CF) sh[t] = g_cnt_f[t];
    __syncthreads();
    for (int o = 1; o < CF; o <<= 1) {
        int v = (t < CF && t >= o) ? sh[t - o] : 0;
        __syncthreads();
        if (t < CF) sh[t] += v;
        __syncthreads();
    }
    if (t < CF) { int e = sh[t] - g_cnt_f[t]; g_off_f[t] = e; g_cur_f[t] = e; }
    __syncthreads();
    // rcl
    if (t < CR) sh[t] = g_cnt_r[t];
    __syncthreads();
    for (int o = 1; o < CR; o <<= 1) {
        int v = (t < CR && t >= o) ? sh[t - o] : 0;
        __syncthreads();
        if (t < CR) sh[t] += v;
        __syncthreads();
    }
    if (t < CR) { int e = sh[t] - g_cnt_r[t]; g_off_r[t] = e; g_cur_r[t] = e; }
}

// ---------------- scatter row indices into class-sorted order ----------------
__global__ void k_scatter(const int* __restrict__ lab, int n,
                          int* __restrict__ cur, int* __restrict__ srt) {
    int i = blockIdx.x * blockDim.x + threadIdx.x;
    if (i < n) {
        int l = lab[i];
        if (l >= 0) {
            int p = atomicAdd(&cur[l], 1);
            srt[p] = i;
        }
    }
}

// ---------------- per-class sum of normalized rows (one block per class) ----------------
__global__ void k_classsum(const float* __restrict__ x, const float* __restrict__ invn,
                           const int* __restrict__ srt, const int* __restrict__ off,
                           const int* __restrict__ cnt, float* __restrict__ sums) {
    int c = blockIdx.x, t = threadIdx.x;
    int s0 = off[c], n = cnt[c];
    float acc = 0.f;
    int r = 0;
    for (; r + 4 <= n; r += 4) {
        int i0 = srt[s0 + r + 0];
        int i1 = srt[s0 + r + 1];
        int i2 = srt[s0 + r + 2];
        int i3 = srt[s0 + r + 3];
        float x0 = x[(size_t)i0 * D + t];
        float x1 = x[(size_t)i1 * D + t];
        float x2 = x[(size_t)i2 * D + t];
        float x3 = x[(size_t)i3 * D + t];
        float w0 = invn[i0], w1 = invn[i1], w2 = invn[i2], w3 = invn[i3];
        acc += x0 * w0; acc += x1 * w1; acc += x2 * w2; acc += x3 * w3;
    }
    for (; r < n; r++) {
        int i0 = srt[s0 + r];
        acc += x[(size_t)i0 * D + t] * invn[i0];
    }
    sums[c * D + t] = acc;
}

// ---------------- prototype EMA update (one block per class) ----------------
__global__ void k_proto(const float* __restrict__ sums, const float* __restrict__ pin,
                        const int* __restrict__ cnt, float* __restrict__ pout) {
    __shared__ float sh[256];
    int c = blockIdx.x, t = threadIdx.x;
    int n = cnt[c];
    float mv = sums[c * D + t] / fmaxf((float)n, 1.f);
    sh[t] = mv * mv;
    __syncthreads();
    #pragma unroll
    for (int o = 128; o; o >>= 1) { if (t < o) sh[t] += sh[t + o]; __syncthreads(); }
    float nm = fmaxf(sqrtf(sh[0]), EPSN);
    __syncthreads();
    mv = mv / nm;
    float p = pin[c * D + t];
    float q = 0.5f * p + 0.5f * mv;
    sh[t] = q * q;
    __syncthreads();
    #pragma unroll
    for (int o = 128; o; o >>= 1) { if (t < o) sh[t] += sh[t + o]; __syncthreads(); }
    float nq = fmaxf(sqrtf(sh[0]), EPSN);
    pout[c * D + t] = (n > 0) ? q / nq : p;
}

// ---------------- fused GEMM + online softmax cross-entropy ----------------
template<int C>
__global__ __launch_bounds__(256, 1) void k_loss(
    const float* __restrict__ X, const float* __restrict__ P,
    const int* __restrict__ lab, const float* __restrict__ invn,
    float* __restrict__ lsum, float* __restrict__ lcnt)
{
    extern __shared__ float smem[];
    float* As       = smem;                 // 128*256
    float* Bs       = As + 128 * 256;       // 16*128
    float* scale_sm = Bs + 16 * 128;        // 128
    float* tgt_sm   = scale_sm + 128;       // 128
    int*   lab_sm   = (int*)(tgt_sm + 128); // 128
    float* red_s    = (float*)(lab_sm + 128); // 16
    float* red_c    = red_s + 16;             // 16

    int tid = threadIdx.x;
    int tx = tid & 15, ty = tid >> 4;
    int row0 = blockIdx.x * 128;

    if (tid < 128) {
        lab_sm[tid]   = lab[row0 + tid];
        scale_sm[tid] = invn[row0 + tid] * INV_T;
        tgt_sm[tid]   = 0.f;
    }
    {
        const float4* Xg = (const float4*)(X + (size_t)row0 * D);
        float4* As4 = (float4*)As;
        #pragma unroll
        for (int i = 0; i < 32; i++) As4[tid + i * 256] = Xg[tid + i * 256];
    }
    __syncthreads();

    float m[8], s[8];
    #pragma unroll
    for (int i = 0; i < 8; i++) { m[i] = -1e30f; s[i] = 0.f; }

    for (int c0 = 0; c0 < C; c0 += 128) {
        unsigned long long acc[8][4];
        #pragma unroll
        for (int i = 0; i < 8; i++)
            #pragma unroll
            for (int j = 0; j < 4; j++) acc[i][j] = 0ull;

        int bcl = tid >> 1;            // class within chunk: 0..127
        int bh  = (tid & 1) * 8;       // k sub-offset: 0 or 8
        const float* Pg = P + (size_t)(c0 + bcl) * D;
        float4 pb0 = *(const float4*)(Pg + bh);
        float4 pb1 = *(const float4*)(Pg + bh + 4);

        for (int kc = 0; kc < 256; kc += 16) {
            __syncthreads();
            Bs[(bh + 0) * 128 + bcl] = pb0.x;
            Bs[(bh + 1) * 128 + bcl] = pb0.y;
            Bs[(bh + 2) * 128 + bcl] = pb0.z;
            Bs[(bh + 3) * 128 + bcl] = pb0.w;
            Bs[(bh + 4) * 128 + bcl] = pb1.x;
            Bs[(bh + 5) * 128 + bcl] = pb1.y;
            Bs[(bh + 6) * 128 + bcl] = pb1.z;
            Bs[(bh + 7) * 128 + bcl] = pb1.w;
            __syncthreads();
            if (kc + 16 < 256) {       // register prefetch of next chunk
                pb0 = *(const float4*)(Pg + kc + 16 + bh);
                pb1 = *(const float4*)(Pg + kc + 16 + bh + 4);
            }
            #pragma unroll
            for (int k = 0; k < 16; k++) {
                const float* brow = Bs + k * 128 + tx * 8;
                unsigned long long b0 = *(const unsigned long long*)(brow + 0);
                unsigned long long b1 = *(const unsigned long long*)(brow + 2);
                unsigned long long b2 = *(const unsigned long long*)(brow + 4);
                unsigned long long b3 = *(const unsigned long long*)(brow + 6);
                #pragma unroll
                for (int i = 0; i < 8; i++) {
                    float a = As[(ty * 8 + i) * D + kc + k];
                    unsigned long long ap = pack2(a, a);
                    fma2(acc[i][0], ap, b0);
                    fma2(acc[i][1], ap, b1);
                    fma2(acc[i][2], ap, b2);
                    fma2(acc[i][3], ap, b3);
                }
            }
        }

        #pragma unroll
        for (int i = 0; i < 8; i++) {
            int r = ty * 8 + i;
            float sc = scale_sm[r];
            float l[8];
            #pragma unroll
            for (int j = 0; j < 4; j++) {
                float2 f = unpack2(acc[i][j]);
                l[2 * j]     = f.x * sc;
                l[2 * j + 1] = f.y * sc;
            }
            float cm = l[0];
            #pragma unroll
            for (int j = 1; j < 8; j++) cm = fmaxf(cm, l[j]);
            #pragma unroll
            for (int o = 1; o < 16; o <<= 1) cm = fmaxf(cm, __shfl_xor_sync(0xffffffffu, cm, o));
            float nm = fmaxf(m[i], cm);
            float es = 0.f;
            #pragma unroll
            for (int j = 0; j < 8; j++) es += __expf(l[j] - nm);
            #pragma unroll
            for (int o = 1; o < 16; o <<= 1) es += __shfl_xor_sync(0xffffffffu, es, o);
            s[i] = s[i] * __expf(m[i] - nm) + es;
            m[i] = nm;
            int lb = lab_sm[r];
            int rel = lb - c0 - tx * 8;
            if ((unsigned)rel < 8u && lb >= c0 && lb < c0 + 128) tgt_sm[r] = l[rel];
        }
    }
    __syncthreads();

    if (tx == 0) {
        float a = 0.f, c = 0.f;
        #pragma unroll
        for (int i = 0; i < 8; i++) {
            int r = ty * 8 + i;
            int lb = lab_sm[r];
            if (lb >= 0) { a += (m[i] + logf(s[i])) - tgt_sm[r]; c += 1.f; }
        }
        red_s[ty] = a; red_c[ty] = c;
    }
    __syncthreads();
    if (tid == 0) {
        float a = 0.f, c = 0.f;
        #pragma unroll
        for (int i = 0; i < 16; i++) { a += red_s[i]; c += red_c[i]; }
        lsum[blockIdx.x] = a;
        lcnt[blockIdx.x] = c;
    }
}

// ---------------- final reduction of per-block partials ----------------
__global__ void k_final(float* __restrict__ out) {
    __shared__ float sh[1024];
    int t = threadIdx.x;
    float v;

    v = (t < NB / 128) ? g_ls_f[t] : 0.f;
    sh[t] = v; __syncthreads();
    #pragma unroll
    for (int o = 512; o; o >>= 1) { if (t < o) sh[t] += sh[t + o]; __syncthreads(); }
    float sf = sh[0]; __syncthreads();

    v = (t < NB / 128) ? g_lc_f[t] : 0.f;
    sh[t] = v; __syncthreads();
    #pragma unroll
    for (int o = 512; o; o >>= 1) { if (t < o) sh[t] += sh[t + o]; __syncthreads(); }
    float cf = sh[0]; __syncthreads();

    v = g_ls_r[t];
    sh[t] = v; __syncthreads();
    #pragma unroll
    for (int o = 512; o; o >>= 1) { if (t < o) sh[t] += sh[t + o]; __syncthreads(); }
    float sr = sh[0]; __syncthreads();

    v = g_lc_r[t];
    sh[t] = v; __syncthreads();
    #pragma unroll
    for (int o = 512; o; o >>= 1) { if (t < o) sh[t] += sh[t + o]; __syncthreads(); }
    float cr = sh[0];

    if (t == 0) {
        out[0] = sf / fmaxf(cf, 1.f);
        out[1] = sr / fmaxf(cr, 1.f);
    }
}

// ---------------- host launcher (graph-capturable, allocation-free) ----------------
extern "C" void kernel_launch(void* const* d_in, const int* in_sizes, int n_in,
                              void* d_out, int out_size) {
    (void)in_sizes; (void)n_in; (void)out_size;
    const float* f_fti = (const float*)d_in[0];
    const float* e_rcl = (const float*)d_in[1];
    const int*   tlab  = (const int*)d_in[2];
    const int*   nlab  = (const int*)d_in[3];
    const float* pf    = (const float*)d_in[4];
    const float* pr    = (const float*)d_in[5];
    float* out = (float*)d_out;

    float *invn_f, *invn_r, *sum_f, *sum_r, *pro_f, *pro_r;
    float *ls_f, *lc_f, *ls_r, *lc_r;
    int *cnt_f, *cnt_r, *off_f, *off_r, *cur_f, *cur_r, *srt_f, *srt_r;
    cudaGetSymbolAddress((void**)&invn_f, g_invn_f);
    cudaGetSymbolAddress((void**)&invn_r, g_invn_r);
    cudaGetSymbolAddress((void**)&cnt_f,  g_cnt_f);
    cudaGetSymbolAddress((void**)&cnt_r,  g_cnt_r);
    cudaGetSymbolAddress((void**)&off_f,  g_off_f);
    cudaGetSymbolAddress((void**)&off_r,  g_off_r);
    cudaGetSymbolAddress((void**)&cur_f,  g_cur_f);
    cudaGetSymbolAddress((void**)&cur_r,  g_cur_r);
    cudaGetSymbolAddress((void**)&srt_f,  g_srt_f);
    cudaGetSymbolAddress((void**)&srt_r,  g_srt_r);
    cudaGetSymbolAddress((void**)&sum_f,  g_sum_f);
    cudaGetSymbolAddress((void**)&sum_r,  g_sum_r);
    cudaGetSymbolAddress((void**)&pro_f,  g_pro_f);
    cudaGetSymbolAddress((void**)&pro_r,  g_pro_r);
    cudaGetSymbolAddress((void**)&ls_f,   g_ls_f);
    cudaGetSymbolAddress((void**)&lc_f,   g_lc_f);
    cudaGetSymbolAddress((void**)&ls_r,   g_ls_r);
    cudaGetSymbolAddress((void**)&lc_r,   g_lc_r);

    const int smem = (128 * 256 + 16 * 128 + 128 + 128 + 128 + 32) * 4;
    cudaFuncSetAttribute(k_loss<CF>, cudaFuncAttributeMaxDynamicSharedMemorySize, smem);
    cudaFuncSetAttribute(k_loss<CR>, cudaFuncAttributeMaxDynamicSharedMemorySize, smem);

    k_zero<<<1, 512>>>();
    k_norm<<<NB / 8, 256>>>(f_fti, invn_f);
    k_norm<<<NR / 8, 256>>>(e_rcl, invn_r);
    k_hist<<<256, 256>>>(tlab, NB, cnt_f, CF);
    k_hist<<<256, 256>>>(nlab, NR, cnt_r, CR);
    k_scan<<<1, 512>>>();
    k_scatter<<<NB / 256, 256>>>(tlab, NB, cur_f, srt_f);
    k_scatter<<<NR / 256, 256>>>(nlab, NR, cur_r, srt_r);
    k_classsum<<<CF, 256>>>(f_fti, invn_f, srt_f, off_f, cnt_f, sum_f);
    k_classsum<<<CR, 256>>>(e_rcl, invn_r, srt_r, off_r, cnt_r, sum_r);
    k_proto<<<CF, 256>>>(sum_f, pf, cnt_f, pro_f);
    k_proto<<<CR, 256>>>(sum_r, pr, cnt_r, pro_r);
    k_loss<CF><<<NB / 128, 256, smem>>>(f_fti, pro_f, tlab, invn_f, ls_f, lc_f);
    k_loss<CR><<<NR / 128, 256, smem>>>(e_rcl, pro_r, nlab, invn_r, ls_r, lc_r);
    k_final<<<1, 1024>>>(out);
}

// round 6
// speedup vs baseline: 1.8394x; 1.8394x over previous
#include <cuda_runtime.h>
#include <cuda_bf16.h>
#include <math.h>
#include <stdint.h>

#define D   256
#define NB  65536
#define NR  131072
#define CF  128
#define CR  512
#define INV_T (1.0f/0.3f)
#define EPSN  1e-12f

// ---------------- scratch (static device globals; no runtime alloc) ----------------
__device__ float g_invn_f[NB];
__device__ float g_invn_r[NR];
__device__ int   g_cnt_f[CF];
__device__ int   g_cnt_r[CR];
__device__ int   g_off_f[CF];
__device__ int   g_off_r[CR];
__device__ int   g_cur_f[CF];
__device__ int   g_cur_r[CR];
__device__ int   g_srt_f[NB];
__device__ int   g_srt_r[NR];
__device__ float g_sum_f[CF*D];
__device__ float g_sum_r[CR*D];
__device__ float g_pro_f[CF*D];
__device__ float g_pro_r[CR*D];
__device__ __nv_bfloat16 g_phi_f[CF*D];
__device__ __nv_bfloat16 g_plo_f[CF*D];
__device__ __nv_bfloat16 g_phi_r[CR*D];
__device__ __nv_bfloat16 g_plo_r[CR*D];
__device__ float g_ls_f[NB/128];
__device__ float g_lc_f[NB/128];
__device__ float g_ls_r[NR/128];
__device__ float g_lc_r[NR/128];

__device__ __forceinline__ uint32_t smem_u32(const void* p) {
    uint32_t a;
    asm("{ .reg .u64 t; cvta.to.shared.u64 t, %1; cvt.u32.u64 %0, t; }" : "=r"(a) : "l"(p));
    return a;
}

#define LDSM_X4(r, addr) \
    asm volatile("ldmatrix.sync.aligned.m8n8.x4.shared.b16 {%0,%1,%2,%3}, [%4];" \
        : "=r"((r)[0]), "=r"((r)[1]), "=r"((r)[2]), "=r"((r)[3]) : "r"(addr))

__device__ __forceinline__ void mma_bf16(float* c, const uint32_t* a, const uint32_t* b) {
    asm volatile(
        "mma.sync.aligned.m16n8k16.row.col.f32.bf16.bf16.f32 "
        "{%0,%1,%2,%3}, {%4,%5,%6,%7}, {%8,%9}, {%0,%1,%2,%3};"
        : "+f"(c[0]), "+f"(c[1]), "+f"(c[2]), "+f"(c[3])
        : "r"(a[0]), "r"(a[1]), "r"(a[2]), "r"(a[3]), "r"(b[0]), "r"(b[1]));
}

// ---------------- zero per-call counters ----------------
__global__ void k_zero() {
    int t = threadIdx.x;
    if (t < CF) g_cnt_f[t] = 0;
    if (t < CR) g_cnt_r[t] = 0;
}

// ---------------- row inverse norms: one warp per row ----------------
__global__ void k_norm(const float* __restrict__ x, float* __restrict__ invn) {
    int row  = blockIdx.x * 8 + (threadIdx.x >> 5);
    int lane = threadIdx.x & 31;
    const float4* p = (const float4*)(x + (size_t)row * D);
    float4 a = p[lane];
    float4 b = p[lane + 32];
    float ss = a.x*a.x + a.y*a.y + a.z*a.z + a.w*a.w
             + b.x*b.x + b.y*b.y + b.z*b.z + b.w*b.w;
    #pragma unroll
    for (int o = 16; o; o >>= 1) ss += __shfl_xor_sync(0xffffffffu, ss, o);
    if (lane == 0) invn[row] = 1.0f / fmaxf(sqrtf(ss), EPSN);
}

// ---------------- label histogram ----------------
__global__ void k_hist(const int* __restrict__ lab, int n, int* __restrict__ cnt, int C) {
    __shared__ int sh[CR];
    for (int i = threadIdx.x; i < C; i += blockDim.x) sh[i] = 0;
    __syncthreads();
    for (int i = blockIdx.x * blockDim.x + threadIdx.x; i < n; i += gridDim.x * blockDim.x) {
        int l = lab[i];
        if (l >= 0) atomicAdd(&sh[l], 1);
    }
    __syncthreads();
    for (int i = threadIdx.x; i < C; i += blockDim.x)
        if (sh[i]) atomicAdd(&cnt[i], sh[i]);
}

// ---------------- exclusive scan ----------------
__global__ void k_scan() {
    __shared__ int sh[CR];
    int t = threadIdx.x;
    if (t < CF) sh[t] = g_cnt_f[t];
    __syncthreads();
    for (int o = 1; o < CF; o <<= 1) {
        int v = (t < CF && t >= o) ? sh[t - o] : 0;
        __syncthreads();
        if (t < CF) sh[t] += v;
        __syncthreads();
    }
    if (t < CF) { int e = sh[t] - g_cnt_f[t]; g_off_f[t] = e; g_cur_f[t] = e; }
    __syncthreads();
    if (t < CR) sh[t] = g_cnt_r[t];
    __syncthreads();
    for (int o = 1; o < CR; o <<= 1) {
        int v = (t < CR && t >= o) ? sh[t - o] : 0;
        __syncthreads();
        if (t < CR) sh[t] += v;
        __syncthreads();
    }
    if (t < CR) { int e = sh[t] - g_cnt_r[t]; g_off_r[t] = e; g_cur_r[t] = e; }
}

// ---------------- scatter indices into class-sorted order ----------------
__global__ void k_scatter(const int* __restrict__ lab, int n,
                          int* __restrict__ cur, int* __restrict__ srt) {
    int i = blockIdx.x * blockDim.x + threadIdx.x;
    if (i < n) {
        int l = lab[i];
        if (l >= 0) {
            int p = atomicAdd(&cur[l], 1);
            srt[p] = i;
        }
    }
}

// ---------------- per-class sum of normalized rows ----------------
__global__ void k_classsum(const float* __restrict__ x, const float* __restrict__ invn,
                           const int* __restrict__ srt, const int* __restrict__ off,
                           const int* __restrict__ cnt, float* __restrict__ sums) {
    int c = blockIdx.x, t = threadIdx.x;
    int s0 = off[c], n = cnt[c];
    float acc = 0.f;
    int r = 0;
    for (; r + 4 <= n; r += 4) {
        int i0 = srt[s0 + r + 0];
        int i1 = srt[s0 + r + 1];
        int i2 = srt[s0 + r + 2];
        int i3 = srt[s0 + r + 3];
        float x0 = x[(size_t)i0 * D + t];
        float x1 = x[(size_t)i1 * D + t];
        float x2 = x[(size_t)i2 * D + t];
        float x3 = x[(size_t)i3 * D + t];
        acc += x0 * invn[i0]; acc += x1 * invn[i1];
        acc += x2 * invn[i2]; acc += x3 * invn[i3];
    }
    for (; r < n; r++) {
        int i0 = srt[s0 + r];
        acc += x[(size_t)i0 * D + t] * invn[i0];
    }
    sums[c * D + t] = acc;
}

// ---------------- prototype EMA update ----------------
__global__ void k_proto(const float* __restrict__ sums, const float* __restrict__ pin,
                        const int* __restrict__ cnt, float* __restrict__ pout) {
    __shared__ float sh[256];
    int c = blockIdx.x, t = threadIdx.x;
    int n = cnt[c];
    float mv = sums[c * D + t] / fmaxf((float)n, 1.f);
    sh[t] = mv * mv;
    __syncthreads();
    #pragma unroll
    for (int o = 128; o; o >>= 1) { if (t < o) sh[t] += sh[t + o]; __syncthreads(); }
    float nm = fmaxf(sqrtf(sh[0]), EPSN);
    __syncthreads();
    mv = mv / nm;
    float p = pin[c * D + t];
    float q = 0.5f * p + 0.5f * mv;
    sh[t] = q * q;
    __syncthreads();
    #pragma unroll
    for (int o = 128; o; o >>= 1) { if (t < o) sh[t] += sh[t + o]; __syncthreads(); }
    float nq = fmaxf(sqrtf(sh[0]), EPSN);
    pout[c * D + t] = (n > 0) ? q / nq : p;
}

// ---------------- fp32 -> bf16 hi/lo split of prototypes ----------------
__global__ void k_cvt(const float* __restrict__ p, __nv_bfloat16* __restrict__ hi,
                      __nv_bfloat16* __restrict__ lo, int n) {
    int i = blockIdx.x * blockDim.x + threadIdx.x;
    if (i < n) {
        float v = p[i];
        __nv_bfloat16 h = __float2bfloat16(v);
        hi[i] = h;
        lo[i] = __float2bfloat16(v - __bfloat162float(h));
    }
}

// ---------------- mma.sync fused GEMM + softmax cross-entropy ----------------
// Per CTA: 128 rows x C classes, K=256, 3xbf16 fp32 emulation
// (Xhi@Phi + Xhi@Plo + Xlo@Phi) on the tensor pipe via m16n8k16.
// 8 warps: wr=wid&3 (32-row band), wc=wid>>2 (64-col band of 128-class chunk).
// A hi/lo resident in padded smem (stride 264 bf16 = 528B, 16B-unit stride 33:
// conflict-free ldmatrix). B chunk streamed per 128-k half (stride 136 bf16 =
// 272B, unit stride 17: conflict-free). Epilogue on fragment layout:
// |logit|<=1/T so plain running sumexp, no max rescale.
// smem map (bytes): 0 scale[128] | 512 lab[128] | 1024 rs[256] | 2048 tg[256]
//   | 3072 red_s[8] | 3104 red_c[8] | 4096 A_hi(67584) | 71680 A_lo(67584)
//   | 139264 B_hi(34816) | 174080 B_lo(34816) | end 208896
#define A_HI_OFF 4096
#define A_LO_OFF 71680
#define B_HI_OFF 139264
#define B_LO_OFF 174080
#define SMEM_LOSS 208896

template<int C>
__global__ __launch_bounds__(256, 1)
void k_loss_wmma(const float* __restrict__ X,
                 const __nv_bfloat16* __restrict__ Phi,
                 const __nv_bfloat16* __restrict__ Plo,
                 const int* __restrict__ lab, const float* __restrict__ invn,
                 float* __restrict__ lsum, float* __restrict__ lcnt)
{
    extern __shared__ char smem[];
    float* scale_sm = (float*)(smem + 0);
    int*   lab_sm   = (int*)(smem + 512);
    float* rs_sm    = (float*)(smem + 1024);
    float* tg_sm    = (float*)(smem + 2048);
    float* red_s    = (float*)(smem + 3072);
    float* red_c    = (float*)(smem + 3104);

    const int tid  = threadIdx.x;
    const int wid  = tid >> 5;
    const int lane = tid & 31;
    const int wr   = wid & 3;
    const int wc   = wid >> 2;
    const int row0 = blockIdx.x * 128;

    if (tid < 128) {
        scale_sm[tid] = invn[row0 + tid] * INV_T;
        lab_sm[tid]   = lab[row0 + tid];
    }

    // ---- load + split A: 128 x 256 fp32 -> bf16 hi/lo, padded stride 264 ----
    #pragma unroll 4
    for (int i = 0; i < 16; i++) {
        int ch = tid + i * 256;           // 8-elem chunk id, 4096 total
        int r  = ch >> 5;                 // row
        int c8 = (ch & 31) * 8;           // col
        const float* src = X + (size_t)(row0 + r) * D + c8;
        float4 v0 = *(const float4*)src;
        float4 v1 = *(const float4*)(src + 4);
        float v[8] = {v0.x, v0.y, v0.z, v0.w, v1.x, v1.y, v1.z, v1.w};
        uint32_t h[8], l[8];
        #pragma unroll
        for (int j = 0; j < 8; j++) {
            __nv_bfloat16 hb = __float2bfloat16(v[j]);
            h[j] = (uint32_t)__bfloat16_as_ushort(hb);
            l[j] = (uint32_t)__bfloat16_as_ushort(__float2bfloat16(v[j] - __bfloat162float(hb)));
        }
        uint4 hv = make_uint4(h[0] | (h[1] << 16), h[2] | (h[3] << 16),
                              h[4] | (h[5] << 16), h[6] | (h[7] << 16));
        uint4 lv = make_uint4(l[0] | (l[1] << 16), l[2] | (l[3] << 16),
                              l[4] | (l[5] << 16), l[6] | (l[7] << 16));
        *(uint4*)(smem + A_HI_OFF + r * 528 + c8 * 2) = hv;
        *(uint4*)(smem + A_LO_OFF + r * 528 + c8 * 2) = lv;
    }

    // per-lane ldmatrix base addresses
    const uint32_t sbu = smem_u32(smem);
    const uint32_t aBase = sbu + A_HI_OFF
        + (uint32_t)(wr * 32 + (lane & 15)) * 528 + (uint32_t)(lane >> 4) * 16;
    const uint32_t bBase = sbu + B_HI_OFF
        + (uint32_t)(wc * 64 + (lane & 7) + ((lane >> 4) & 1) * 8) * 272
        + (uint32_t)((lane >> 3) & 1) * 16;

    // owned rows (fragment layout): r(mt,h) = wr*32 + mt*16 + (lane>>2) + h*8
    float sc4[4]; int lb4[4];
    #pragma unroll
    for (int mt = 0; mt < 2; mt++)
        #pragma unroll
        for (int h = 0; h < 2; h++) {
            int r = wr * 32 + mt * 16 + (lane >> 2) + h * 8;
            // scale/lab written above by tid<128; ensure visibility
            sc4[mt * 2 + h] = 0.f; lb4[mt * 2 + h] = r; // placeholder, reload after sync
        }
    __syncthreads();
    #pragma unroll
    for (int i = 0; i < 4; i++) { int r = lb4[i]; sc4[i] = scale_sm[r]; lb4[i] = lab_sm[r]; }

    float ssum[4] = {0.f, 0.f, 0.f, 0.f};
    float tgt[4]  = {0.f, 0.f, 0.f, 0.f};

    for (int c0 = 0; c0 < C; c0 += 128) {
        float acc[2][8][4];
        #pragma unroll
        for (int mt = 0; mt < 2; mt++)
            #pragma unroll
            for (int nt = 0; nt < 8; nt++)
                #pragma unroll
                for (int e = 0; e < 4; e++) acc[mt][nt][e] = 0.f;

        for (int kh = 0; kh < 2; kh++) {
            __syncthreads();   // prior chunk/half consumers done before overwrite
            // ---- load B half: 128 classes x 128 k, hi & lo ----
            #pragma unroll 2
            for (int i = 0; i < 8; i++) {
                int ch = tid + i * 256;    // 2048 chunks of 8
                int r  = ch >> 4;
                int c8 = (ch & 15) * 8;
                size_t g = (size_t)(c0 + r) * D + kh * 128 + c8;
                *(uint4*)(smem + B_HI_OFF + r * 272 + c8 * 2) = *(const uint4*)(Phi + g);
                *(uint4*)(smem + B_LO_OFF + r * 272 + c8 * 2) = *(const uint4*)(Plo + g);
            }
            __syncthreads();
            #pragma unroll
            for (int k16 = 0; k16 < 8; k16++) {
                uint32_t aoff = (uint32_t)(kh * 128 + k16 * 16) * 2;
                uint32_t ah0[4], ah1[4], al0[4], al1[4];
                LDSM_X4(ah0, aBase + aoff);
                LDSM_X4(ah1, aBase + 8448 + aoff);
                LDSM_X4(al0, aBase + 67584 + aoff);
                LDSM_X4(al1, aBase + 67584 + 8448 + aoff);
                #pragma unroll
                for (int ntp = 0; ntp < 4; ntp++) {
                    uint32_t boff = (uint32_t)ntp * 4352 + (uint32_t)k16 * 32;
                    uint32_t bh[4], bl[4];
                    LDSM_X4(bh, bBase + boff);
                    LDSM_X4(bl, bBase + 34816 + boff);
                    mma_bf16(acc[0][ntp*2],   ah0, bh);
                    mma_bf16(acc[1][ntp*2],   ah1, bh);
                    mma_bf16(acc[0][ntp*2+1], ah0, bh + 2);
                    mma_bf16(acc[1][ntp*2+1], ah1, bh + 2);
                    mma_bf16(acc[0][ntp*2],   ah0, bl);
                    mma_bf16(acc[1][ntp*2],   ah1, bl);
                    mma_bf16(acc[0][ntp*2+1], ah0, bl + 2);
                    mma_bf16(acc[1][ntp*2+1], ah1, bl + 2);
                    mma_bf16(acc[0][ntp*2],   al0, bh);
                    mma_bf16(acc[1][ntp*2],   al1, bh);
                    mma_bf16(acc[0][ntp*2+1], al0, bh + 2);
                    mma_bf16(acc[1][ntp*2+1], al1, bh + 2);
                }
            }
        }
        // ---- epilogue on fragment layout ----
        #pragma unroll
        for (int mt = 0; mt < 2; mt++)
            #pragma unroll
            for (int nt = 0; nt < 8; nt++) {
                int colb = c0 + wc * 64 + nt * 8 + (lane & 3) * 2;
                float l0 = acc[mt][nt][0] * sc4[mt*2];
                float l1 = acc[mt][nt][1] * sc4[mt*2];
                float l2 = acc[mt][nt][2] * sc4[mt*2+1];
                float l3 = acc[mt][nt][3] * sc4[mt*2+1];
                ssum[mt*2]   += __expf(l0) + __expf(l1);
                ssum[mt*2+1] += __expf(l2) + __expf(l3);
                if (lb4[mt*2]   == colb)     tgt[mt*2]   = l0;
                if (lb4[mt*2]   == colb + 1) tgt[mt*2]   = l1;
                if (lb4[mt*2+1] == colb)     tgt[mt*2+1] = l2;
                if (lb4[mt*2+1] == colb + 1) tgt[mt*2+1] = l3;
            }
    }

    // ---- reduce across the 4 lanes sharing each row ----
    #pragma unroll
    for (int i = 0; i < 4; i++) {
        ssum[i] += __shfl_xor_sync(0xffffffffu, ssum[i], 1);
        ssum[i] += __shfl_xor_sync(0xffffffffu, ssum[i], 2);
        tgt[i]  += __shfl_xor_sync(0xffffffffu, tgt[i], 1);
        tgt[i]  += __shfl_xor_sync(0xffffffffu, tgt[i], 2);
    }
    if ((lane & 3) == 0) {
        #pragma unroll
        for (int i = 0; i < 4; i++) {
            int r = wr * 32 + (i >> 1) * 16 + (lane >> 2) + (i & 1) * 8;
            rs_sm[r * 2 + wc] = ssum[i];
            tg_sm[r * 2 + wc] = tgt[i];
        }
    }
    __syncthreads();

    // ---- per-row loss, block reduce ----
    float v = 0.f, cn = 0.f;
    if (tid < 128) {
        int lb = lab_sm[tid];
        if (lb >= 0) {
            float S = rs_sm[tid * 2] + rs_sm[tid * 2 + 1];
            float T = tg_sm[tid * 2] + tg_sm[tid * 2 + 1];
            v = logf(S) - T;
            cn = 1.f;
        }
    }
    #pragma unroll
    for (int o = 16; o; o >>= 1) {
        v  += __shfl_xor_sync(0xffffffffu, v, o);
        cn += __shfl_xor_sync(0xffffffffu, cn, o);
    }
    if (lane == 0) { red_s[wid] = v; red_c[wid] = cn; }
    __syncthreads();
    if (tid == 0) {
        lsum[blockIdx.x] = red_s[0] + red_s[1] + red_s[2] + red_s[3];
        lcnt[blockIdx.x] = red_c[0] + red_c[1] + red_c[2] + red_c[3];
    }
}

// ---------------- final reduction of per-block partials ----------------
__global__ void k_final(float* __restrict__ out) {
    __shared__ float sh[1024];
    int t = threadIdx.x;
    float v;

    v = (t < NB / 128) ? g_ls_f[t] : 0.f;
    sh[t] = v; __syncthreads();
    #pragma unroll
    for (int o = 512; o; o >>= 1) { if (t < o) sh[t] += sh[t + o]; __syncthreads(); }
    float sf = sh[0]; __syncthreads();

    v = (t < NB / 128) ? g_lc_f[t] : 0.f;
    sh[t] = v; __syncthreads();
    #pragma unroll
    for (int o = 512; o; o >>= 1) { if (t < o) sh[t] += sh[t + o]; __syncthreads(); }
    float cf = sh[0]; __syncthreads();

    v = g_ls_r[t];
    sh[t] = v; __syncthreads();
    #pragma unroll
    for (int o = 512; o; o >>= 1) { if (t < o) sh[t] += sh[t + o]; __syncthreads(); }
    float sr = sh[0]; __syncthreads();

    v = g_lc_r[t];
    sh[t] = v; __syncthreads();
    #pragma unroll
    for (int o = 512; o; o >>= 1) { if (t < o) sh[t] += sh[t + o]; __syncthreads(); }
    float cr = sh[0];

    if (t == 0) {
        out[0] = sf / fmaxf(cf, 1.f);
        out[1] = sr / fmaxf(cr, 1.f);
    }
}

// ---------------- host launcher (graph-capturable, allocation-free) ----------------
extern "C" void kernel_launch(void* const* d_in, const int* in_sizes, int n_in,
                              void* d_out, int out_size) {
    (void)in_sizes; (void)n_in; (void)out_size;
    const float* f_fti = (const float*)d_in[0];
    const float* e_rcl = (const float*)d_in[1];
    const int*   tlab  = (const int*)d_in[2];
    const int*   nlab  = (const int*)d_in[3];
    const float* pf    = (const float*)d_in[4];
    const float* pr    = (const float*)d_in[5];
    float* out = (float*)d_out;

    float *invn_f, *invn_r, *sum_f, *sum_r, *pro_f, *pro_r;
    float *ls_f, *lc_f, *ls_r, *lc_r;
    int *cnt_f, *cnt_r, *off_f, *off_r, *cur_f, *cur_r, *srt_f, *srt_r;
    __nv_bfloat16 *phi_f, *plo_f, *phi_r, *plo_r;
    cudaGetSymbolAddress((void**)&invn_f, g_invn_f);
    cudaGetSymbolAddress((void**)&invn_r, g_invn_r);
    cudaGetSymbolAddress((void**)&cnt_f,  g_cnt_f);
    cudaGetSymbolAddress((void**)&cnt_r,  g_cnt_r);
    cudaGetSymbolAddress((void**)&off_f,  g_off_f);
    cudaGetSymbolAddress((void**)&off_r,  g_off_r);
    cudaGetSymbolAddress((void**)&cur_f,  g_cur_f);
    cudaGetSymbolAddress((void**)&cur_r,  g_cur_r);
    cudaGetSymbolAddress((void**)&srt_f,  g_srt_f);
    cudaGetSymbolAddress((void**)&srt_r,  g_srt_r);
    cudaGetSymbolAddress((void**)&sum_f,  g_sum_f);
    cudaGetSymbolAddress((void**)&sum_r,  g_sum_r);
    cudaGetSymbolAddress((void**)&pro_f,  g_pro_f);
    cudaGetSymbolAddress((void**)&pro_r,  g_pro_r);
    cudaGetSymbolAddress((void**)&phi_f,  g_phi_f);
    cudaGetSymbolAddress((void**)&plo_f,  g_plo_f);
    cudaGetSymbolAddress((void**)&phi_r,  g_phi_r);
    cudaGetSymbolAddress((void**)&plo_r,  g_plo_r);
    cudaGetSymbolAddress((void**)&ls_f,   g_ls_f);
    cudaGetSymbolAddress((void**)&lc_f,   g_lc_f);
    cudaGetSymbolAddress((void**)&ls_r,   g_ls_r);
    cudaGetSymbolAddress((void**)&lc_r,   g_lc_r);

    cudaFuncSetAttribute(k_loss_wmma<CF>, cudaFuncAttributeMaxDynamicSharedMemorySize, SMEM_LOSS);
    cudaFuncSetAttribute(k_loss_wmma<CR>, cudaFuncAttributeMaxDynamicSharedMemorySize, SMEM_LOSS);

    k_zero<<<1, 512>>>();
    k_norm<<<NB / 8, 256>>>(f_fti, invn_f);
    k_norm<<<NR / 8, 256>>>(e_rcl, invn_r);
    k_hist<<<256, 256>>>(tlab, NB, cnt_f, CF);
    k_hist<<<256, 256>>>(nlab, NR, cnt_r, CR);
    k_scan<<<1, 512>>>();
    k_scatter<<<NB / 256, 256>>>(tlab, NB, cur_f, srt_f);
    k_scatter<<<NR / 256, 256>>>(nlab, NR, cur_r, srt_r);
    k_classsum<<<CF, 256>>>(f_fti, invn_f, srt_f, off_f, cnt_f, sum_f);
    k_classsum<<<CR, 256>>>(e_rcl, invn_r, srt_r, off_r, cnt_r, sum_r);
    k_proto<<<CF, 256>>>(sum_f, pf, cnt_f, pro_f);
    k_proto<<<CR, 256>>>(sum_r, pr, cnt_r, pro_r);
    k_cvt<<<(CF * D + 255) / 256, 256>>>(pro_f, phi_f, plo_f, CF * D);
    k_cvt<<<(CR * D + 255) / 256, 256>>>(pro_r, phi_r, plo_r, CR * D);
    k_loss_wmma<CF><<<NB / 128, 256, SMEM_LOSS>>>(f_fti, phi_f, plo_f, tlab, invn_f, ls_f, lc_f);
    k_loss_wmma<CR><<<NR / 128, 256, SMEM_LOSS>>>(e_rcl, phi_r, plo_r, nlab, invn_r, ls_r, lc_r);
    k_final<<<1, 1024>>>(out);
}

// round 7
// speedup vs baseline: 3.0313x; 1.6480x over previous
#include <cuda_runtime.h>
#include <cuda_bf16.h>
#include <math.h>
#include <stdint.h>

#define D   256
#define NB  65536
#define NR  131072
#define CF  128
#define CR  512
#define EPSN  1e-12f
// (1/T) * log2(e)  — folds temperature and base-2 exp into one constant
#define SC2 4.8089834696296117f
#define LN2 0.6931471805599453f

// ---------------- scratch (static device globals; no runtime alloc) ----------------
__device__ __nv_bfloat16 g_xn_f[NB*D];   // normalized features, bf16
__device__ __nv_bfloat16 g_xn_r[NR*D];
__device__ int   g_cnt_f[CF];
__device__ int   g_cnt_r[CR];
__device__ int   g_off_f[CF];
__device__ int   g_off_r[CR];
__device__ int   g_cur_f[CF];
__device__ int   g_cur_r[CR];
__device__ int   g_srt_f[NB];
__device__ int   g_srt_r[NR];
__device__ float g_sum_f[CF*D];
__device__ float g_sum_r[CR*D];
__device__ __nv_bfloat16 g_pb_f[CF*D];   // updated prototypes, bf16
__device__ __nv_bfloat16 g_pb_r[CR*D];
__device__ float g_ls_f[NB/128];
__device__ float g_lc_f[NB/128];
__device__ float g_ls_r[NR/128];
__device__ float g_lc_r[NR/128];

__device__ __forceinline__ uint32_t smem_u32(const void* p) {
    uint32_t a;
    asm("{ .reg .u64 t; cvta.to.shared.u64 t, %1; cvt.u32.u64 %0, t; }" : "=r"(a) : "l"(p));
    return a;
}
__device__ __forceinline__ uint32_t pack_bf2(float x, float y) {
    __nv_bfloat162 v = __floats2bfloat162_rn(x, y);
    return *reinterpret_cast<uint32_t*>(&v);
}
__device__ __forceinline__ float ex2f_fast(float x) {
    float r; asm("ex2.approx.f32 %0, %1;" : "=f"(r) : "f"(x)); return r;
}
__device__ __forceinline__ float lg2f_fast(float x) {
    float r; asm("lg2.approx.f32 %0, %1;" : "=f"(r) : "f"(x)); return r;
}

#define LDSM_X4(r, addr) \
    asm volatile("ldmatrix.sync.aligned.m8n8.x4.shared.b16 {%0,%1,%2,%3}, [%4];" \
        : "=r"((r)[0]), "=r"((r)[1]), "=r"((r)[2]), "=r"((r)[3]) : "r"(addr))

__device__ __forceinline__ void mma_bf16(float* c, const uint32_t* a, const uint32_t* b) {
    asm volatile(
        "mma.sync.aligned.m16n8k16.row.col.f32.bf16.bf16.f32 "
        "{%0,%1,%2,%3}, {%4,%5,%6,%7}, {%8,%9}, {%0,%1,%2,%3};"
        : "+f"(c[0]), "+f"(c[1]), "+f"(c[2]), "+f"(c[3])
        : "r"(a[0]), "r"(a[1]), "r"(a[2]), "r"(a[3]), "r"(b[0]), "r"(b[1]));
}

#define CP_COMMIT() asm volatile("cp.async.commit_group;" ::: "memory")
#define CP_WAIT0()  asm volatile("cp.async.wait_group 0;" ::: "memory")

// ---------------- zero per-call counters ----------------
__global__ void k_zero() {
    int t = threadIdx.x;
    if (t < CF) g_cnt_f[t] = 0;
    if (t < CR) g_cnt_r[t] = 0;
}

// ---------------- normalize rows, write bf16: one warp per row ----------------
__global__ void k_norm_cvt(const float* __restrict__ x, __nv_bfloat16* __restrict__ xn) {
    int row  = blockIdx.x * 8 + (threadIdx.x >> 5);
    int lane = threadIdx.x & 31;
    const float4* p = (const float4*)(x + (size_t)row * D);
    float4 a = p[lane];
    float4 b = p[lane + 32];
    float ss = a.x*a.x + a.y*a.y + a.z*a.z + a.w*a.w
             + b.x*b.x + b.y*b.y + b.z*b.z + b.w*b.w;
    #pragma unroll
    for (int o = 16; o; o >>= 1) ss += __shfl_xor_sync(0xffffffffu, ss, o);
    float inv = 1.0f / fmaxf(sqrtf(ss), EPSN);
    uint32_t* o32 = (uint32_t*)(xn + (size_t)row * D);
    o32[lane * 2 + 0]  = pack_bf2(a.x * inv, a.y * inv);
    o32[lane * 2 + 1]  = pack_bf2(a.z * inv, a.w * inv);
    o32[64 + lane * 2] = pack_bf2(b.x * inv, b.y * inv);
    o32[65 + lane * 2] = pack_bf2(b.z * inv, b.w * inv);
}

// ---------------- label histogram ----------------
__global__ void k_hist(const int* __restrict__ lab, int n, int* __restrict__ cnt, int C) {
    __shared__ int sh[CR];
    for (int i = threadIdx.x; i < C; i += blockDim.x) sh[i] = 0;
    __syncthreads();
    for (int i = blockIdx.x * blockDim.x + threadIdx.x; i < n; i += gridDim.x * blockDim.x) {
        int l = lab[i];
        if (l >= 0) atomicAdd(&sh[l], 1);
    }
    __syncthreads();
    for (int i = threadIdx.x; i < C; i += blockDim.x)
        if (sh[i]) atomicAdd(&cnt[i], sh[i]);
}

// ---------------- exclusive scan ----------------
__global__ void k_scan() {
    __shared__ int sh[CR];
    int t = threadIdx.x;
    if (t < CF) sh[t] = g_cnt_f[t];
    __syncthreads();
    for (int o = 1; o < CF; o <<= 1) {
        int v = (t < CF && t >= o) ? sh[t - o] : 0;
        __syncthreads();
        if (t < CF) sh[t] += v;
        __syncthreads();
    }
    if (t < CF) { int e = sh[t] - g_cnt_f[t]; g_off_f[t] = e; g_cur_f[t] = e; }
    __syncthreads();
    if (t < CR) sh[t] = g_cnt_r[t];
    __syncthreads();
    for (int o = 1; o < CR; o <<= 1) {
        int v = (t < CR && t >= o) ? sh[t - o] : 0;
        __syncthreads();
        if (t < CR) sh[t] += v;
        __syncthreads();
    }
    if (t < CR) { int e = sh[t] - g_cnt_r[t]; g_off_r[t] = e; g_cur_r[t] = e; }
}

// ---------------- scatter indices into class-sorted order ----------------
__global__ void k_scatter(const int* __restrict__ lab, int n,
                          int* __restrict__ cur, int* __restrict__ srt) {
    int i = blockIdx.x * blockDim.x + threadIdx.x;
    if (i < n) {
        int l = lab[i];
        if (l >= 0) {
            int p = atomicAdd(&cur[l], 1);
            srt[p] = i;
        }
    }
}

// ---------------- per-class sum of normalized bf16 rows ----------------
__global__ void k_classsum(const __nv_bfloat16* __restrict__ xn,
                           const int* __restrict__ srt, const int* __restrict__ off,
                           const int* __restrict__ cnt, float* __restrict__ sums) {
    int c = blockIdx.x, t = threadIdx.x;
    int s0 = off[c], n = cnt[c];
    float acc = 0.f;
    int r = 0;
    for (; r + 4 <= n; r += 4) {
        int i0 = srt[s0 + r + 0];
        int i1 = srt[s0 + r + 1];
        int i2 = srt[s0 + r + 2];
        int i3 = srt[s0 + r + 3];
        float x0 = __bfloat162float(xn[(size_t)i0 * D + t]);
        float x1 = __bfloat162float(xn[(size_t)i1 * D + t]);
        float x2 = __bfloat162float(xn[(size_t)i2 * D + t]);
        float x3 = __bfloat162float(xn[(size_t)i3 * D + t]);
        acc += x0; acc += x1; acc += x2; acc += x3;
    }
    for (; r < n; r++) {
        int i0 = srt[s0 + r];
        acc += __bfloat162float(xn[(size_t)i0 * D + t]);
    }
    sums[c * D + t] = acc;
}

// ---------------- prototype EMA update -> bf16 ----------------
__global__ void k_proto(const float* __restrict__ sums, const float* __restrict__ pin,
                        const int* __restrict__ cnt, __nv_bfloat16* __restrict__ pout) {
    __shared__ float sh[256];
    int c = blockIdx.x, t = threadIdx.x;
    int n = cnt[c];
    float mv = sums[c * D + t] / fmaxf((float)n, 1.f);
    sh[t] = mv * mv;
    __syncthreads();
    #pragma unroll
    for (int o = 128; o; o >>= 1) { if (t < o) sh[t] += sh[t + o]; __syncthreads(); }
    float nm = fmaxf(sqrtf(sh[0]), EPSN);
    __syncthreads();
    mv = mv / nm;
    float p = pin[c * D + t];
    float q = 0.5f * p + 0.5f * mv;
    sh[t] = q * q;
    __syncthreads();
    #pragma unroll
    for (int o = 128; o; o >>= 1) { if (t < o) sh[t] += sh[t + o]; __syncthreads(); }
    float nq = fmaxf(sqrtf(sh[0]), EPSN);
    pout[c * D + t] = __float2bfloat16((n > 0) ? q / nq : p);
}

// ---------------- single-bf16 mma.sync fused GEMM + softmax CE ----------------
// Per CTA: 128 rows x C classes, K=256. A (normalized bf16) resident in padded
// smem (stride 528B, conflict-free ldmatrix); B per-128-class chunk double-
// buffered via cp.async. 8 warps 4x2: wr row-band(32), wc col-band(64).
// Logits = dot * 1/T, constant scale; base-2 online sumexp (|l2|<=4.81, no max).
// smem map: 0 lab[128] | 512 rs[256] | 1536 tg[256] | 2560 red_s | 2592 red_c
//           4096 A(67584) | 71680 B0(67584) | 139264 B1(67584) -> 206848
#define A_OFF   4096
#define B0_OFF  71680
#define BBUF    67584
#define SMEM_LOSS 206848

__device__ __forceinline__ void prefetch_B(uint32_t sbu, uint32_t dstOff,
                                           const __nv_bfloat16* __restrict__ P,
                                           int c0, int tid) {
    #pragma unroll
    for (int i = 0; i < 16; i++) {
        int ch = tid + i * 256;           // 4096 chunks of 8 bf16
        int r  = ch >> 5;                 // class row 0..127
        int c8 = (ch & 31) * 8;           // k col 0..248
        uint32_t dst = sbu + dstOff + (uint32_t)(r * 528 + c8 * 2);
        const void* src = P + (size_t)(c0 + r) * D + c8;
        asm volatile("cp.async.cg.shared.global [%0], [%1], 16;" :: "r"(dst), "l"(src));
    }
}

template<int C>
__global__ __launch_bounds__(256, 1)
void k_loss_tc(const __nv_bfloat16* __restrict__ Xn,
               const __nv_bfloat16* __restrict__ Pb,
               const int* __restrict__ lab,
               float* __restrict__ lsum, float* __restrict__ lcnt)
{
    extern __shared__ char smem[];
    int*   lab_sm = (int*)(smem + 0);
    float* rs_sm  = (float*)(smem + 512);
    float* tg_sm  = (float*)(smem + 1536);
    float* red_s  = (float*)(smem + 2560);
    float* red_c  = (float*)(smem + 2592);

    const int tid  = threadIdx.x;
    const int wid  = tid >> 5;
    const int lane = tid & 31;
    const int wr   = wid & 3;
    const int wc   = wid >> 2;
    const int row0 = blockIdx.x * 128;
    const uint32_t sbu = smem_u32(smem);

    if (tid < 128) lab_sm[tid] = lab[row0 + tid];

    // ---- A copy: 128 x 256 bf16, padded stride 528B ----
    #pragma unroll
    for (int i = 0; i < 16; i++) {
        int ch = tid + i * 256;
        int r  = ch >> 5;
        int c8 = (ch & 31) * 8;
        *(uint4*)(smem + A_OFF + r * 528 + c8 * 2) =
            *(const uint4*)(Xn + (size_t)(row0 + r) * D + c8);
    }

    prefetch_B(sbu, B0_OFF, Pb, 0, tid);
    CP_COMMIT();
    CP_WAIT0();
    __syncthreads();   // chunk0 + A + labels visible to all

    int lb4[4];
    #pragma unroll
    for (int mt = 0; mt < 2; mt++)
        #pragma unroll
        for (int h = 0; h < 2; h++)
            lb4[mt * 2 + h] = lab_sm[wr * 32 + mt * 16 + (lane >> 2) + h * 8];

    const uint32_t aBase = sbu + A_OFF
        + (uint32_t)(wr * 32 + (lane & 15)) * 528 + (uint32_t)(lane >> 4) * 16;
    const uint32_t bB0 = sbu + B0_OFF
        + (uint32_t)(wc * 64 + (lane & 7) + ((lane >> 4) & 1) * 8) * 528
        + (uint32_t)((lane >> 3) & 1) * 16;

    float ssum[4] = {0.f, 0.f, 0.f, 0.f};
    float tgt[4]  = {0.f, 0.f, 0.f, 0.f};

    const int NCH = C / 128;
    for (int c = 0; c < NCH; c++) {
        if (c) { CP_WAIT0(); __syncthreads(); }
        if (c + 1 < NCH) {
            prefetch_B(sbu, B0_OFF + (uint32_t)((c + 1) & 1) * BBUF, Pb, (c + 1) * 128, tid);
            CP_COMMIT();
        }
        const uint32_t bBase = bB0 + (uint32_t)(c & 1) * BBUF;

        float acc[2][8][4];
        #pragma unroll
        for (int mt = 0; mt < 2; mt++)
            #pragma unroll
            for (int nt = 0; nt < 8; nt++)
                #pragma unroll
                for (int e = 0; e < 4; e++) acc[mt][nt][e] = 0.f;

        #pragma unroll
        for (int k16 = 0; k16 < 16; k16++) {
            uint32_t aoff = (uint32_t)k16 * 32;
            uint32_t ah0[4], ah1[4];
            LDSM_X4(ah0, aBase + aoff);
            LDSM_X4(ah1, aBase + 8448 + aoff);
            #pragma unroll
            for (int ntp = 0; ntp < 4; ntp++) {
                uint32_t bh[4];
                LDSM_X4(bh, bBase + (uint32_t)ntp * 8448 + aoff);
                mma_bf16(acc[0][ntp*2],   ah0, bh);
                mma_bf16(acc[1][ntp*2],   ah1, bh);
                mma_bf16(acc[0][ntp*2+1], ah0, bh + 2);
                mma_bf16(acc[1][ntp*2+1], ah1, bh + 2);
            }
        }

        // ---- epilogue: base-2 sumexp + target capture (fragment layout) ----
        int c0 = c * 128;
        #pragma unroll
        for (int mt = 0; mt < 2; mt++)
            #pragma unroll
            for (int nt = 0; nt < 8; nt++) {
                int colb = c0 + wc * 64 + nt * 8 + (lane & 3) * 2;
                float l0 = acc[mt][nt][0] * SC2;
                float l1 = acc[mt][nt][1] * SC2;
                float l2 = acc[mt][nt][2] * SC2;
                float l3 = acc[mt][nt][3] * SC2;
                ssum[mt*2]   += ex2f_fast(l0) + ex2f_fast(l1);
                ssum[mt*2+1] += ex2f_fast(l2) + ex2f_fast(l3);
                if (lb4[mt*2]   == colb)     tgt[mt*2]   = l0;
                if (lb4[mt*2]   == colb + 1) tgt[mt*2]   = l1;
                if (lb4[mt*2+1] == colb)     tgt[mt*2+1] = l2;
                if (lb4[mt*2+1] == colb + 1) tgt[mt*2+1] = l3;
            }
    }

    // ---- reduce across 4 lanes sharing each row ----
    #pragma unroll
    for (int i = 0; i < 4; i++) {
        ssum[i] += __shfl_xor_sync(0xffffffffu, ssum[i], 1);
        ssum[i] += __shfl_xor_sync(0xffffffffu, ssum[i], 2);
        tgt[i]  += __shfl_xor_sync(0xffffffffu, tgt[i], 1);
        tgt[i]  += __shfl_xor_sync(0xffffffffu, tgt[i], 2);
    }
    if ((lane & 3) == 0) {
        #pragma unroll
        for (int i = 0; i < 4; i++) {
            int r = wr * 32 + (i >> 1) * 16 + (lane >> 2) + (i & 1) * 8;
            rs_sm[r * 2 + wc] = ssum[i];
            tg_sm[r * 2 + wc] = tgt[i];
        }
    }
    __syncthreads();

    // ---- per-row loss, block reduce ----
    float v = 0.f, cn = 0.f;
    if (tid < 128) {
        int lb = lab_sm[tid];
        if (lb >= 0) {
            float S  = rs_sm[tid * 2] + rs_sm[tid * 2 + 1];
            float T2 = tg_sm[tid * 2] + tg_sm[tid * 2 + 1];
            v  = LN2 * (lg2f_fast(S) - T2);
            cn = 1.f;
        }
    }
    #pragma unroll
    for (int o = 16; o; o >>= 1) {
        v  += __shfl_xor_sync(0xffffffffu, v, o);
        cn += __shfl_xor_sync(0xffffffffu, cn, o);
    }
    if (lane == 0) { red_s[wid] = v; red_c[wid] = cn; }
    __syncthreads();
    if (tid == 0) {
        lsum[blockIdx.x] = red_s[0] + red_s[1] + red_s[2] + red_s[3];
        lcnt[blockIdx.x] = red_c[0] + red_c[1] + red_c[2] + red_c[3];
    }
}

// ---------------- final reduction of per-block partials ----------------
__global__ void k_final(float* __restrict__ out) {
    __shared__ float sh[1024];
    int t = threadIdx.x;
    float v;

    v = (t < NB / 128) ? g_ls_f[t] : 0.f;
    sh[t] = v; __syncthreads();
    #pragma unroll
    for (int o = 512; o; o >>= 1) { if (t < o) sh[t] += sh[t + o]; __syncthreads(); }
    float sf = sh[0]; __syncthreads();

    v = (t < NB / 128) ? g_lc_f[t] : 0.f;
    sh[t] = v; __syncthreads();
    #pragma unroll
    for (int o = 512; o; o >>= 1) { if (t < o) sh[t] += sh[t + o]; __syncthreads(); }
    float cf = sh[0]; __syncthreads();

    v = g_ls_r[t];
    sh[t] = v; __syncthreads();
    #pragma unroll
    for (int o = 512; o; o >>= 1) { if (t < o) sh[t] += sh[t + o]; __syncthreads(); }
    float sr = sh[0]; __syncthreads();

    v = g_lc_r[t];
    sh[t] = v; __syncthreads();
    #pragma unroll
    for (int o = 512; o; o >>= 1) { if (t < o) sh[t] += sh[t + o]; __syncthreads(); }
    float cr = sh[0];

    if (t == 0) {
        out[0] = sf / fmaxf(cf, 1.f);
        out[1] = sr / fmaxf(cr, 1.f);
    }
}

// ---------------- host launcher (graph-capturable, allocation-free) ----------------
extern "C" void kernel_launch(void* const* d_in, const int* in_sizes, int n_in,
                              void* d_out, int out_size) {
    (void)in_sizes; (void)n_in; (void)out_size;
    const float* f_fti = (const float*)d_in[0];
    const float* e_rcl = (const float*)d_in[1];
    const int*   tlab  = (const int*)d_in[2];
    const int*   nlab  = (const int*)d_in[3];
    const float* pf    = (const float*)d_in[4];
    const float* pr    = (const float*)d_in[5];
    float* out = (float*)d_out;

    __nv_bfloat16 *xn_f, *xn_r, *pb_f, *pb_r;
    float *sum_f, *sum_r, *ls_f, *lc_f, *ls_r, *lc_r;
    int *cnt_f, *cnt_r, *off_f, *off_r, *cur_f, *cur_r, *srt_f, *srt_r;
    cudaGetSymbolAddress((void**)&xn_f,  g_xn_f);
    cudaGetSymbolAddress((void**)&xn_r,  g_xn_r);
    cudaGetSymbolAddress((void**)&cnt_f, g_cnt_f);
    cudaGetSymbolAddress((void**)&cnt_r, g_cnt_r);
    cudaGetSymbolAddress((void**)&off_f, g_off_f);
    cudaGetSymbolAddress((void**)&off_r, g_off_r);
    cudaGetSymbolAddress((void**)&cur_f, g_cur_f);
    cudaGetSymbolAddress((void**)&cur_r, g_cur_r);
    cudaGetSymbolAddress((void**)&srt_f, g_srt_f);
    cudaGetSymbolAddress((void**)&srt_r, g_srt_r);
    cudaGetSymbolAddress((void**)&sum_f, g_sum_f);
    cudaGetSymbolAddress((void**)&sum_r, g_sum_r);
    cudaGetSymbolAddress((void**)&pb_f,  g_pb_f);
    cudaGetSymbolAddress((void**)&pb_r,  g_pb_r);
    cudaGetSymbolAddress((void**)&ls_f,  g_ls_f);
    cudaGetSymbolAddress((void**)&lc_f,  g_lc_f);
    cudaGetSymbolAddress((void**)&ls_r,  g_ls_r);
    cudaGetSymbolAddress((void**)&lc_r,  g_lc_r);

    cudaFuncSetAttribute(k_loss_tc<CF>, cudaFuncAttributeMaxDynamicSharedMemorySize, SMEM_LOSS);
    cudaFuncSetAttribute(k_loss_tc<CR>, cudaFuncAttributeMaxDynamicSharedMemorySize, SMEM_LOSS);

    k_zero<<<1, 512>>>();
    k_norm_cvt<<<NB / 8, 256>>>(f_fti, xn_f);
    k_norm_cvt<<<NR / 8, 256>>>(e_rcl, xn_r);
    k_hist<<<256, 256>>>(tlab, NB, cnt_f, CF);
    k_hist<<<256, 256>>>(nlab, NR, cnt_r, CR);
    k_scan<<<1, 512>>>();
    k_scatter<<<NB / 256, 256>>>(tlab, NB, cur_f, srt_f);
    k_scatter<<<NR / 256, 256>>>(nlab, NR, cur_r, srt_r);
    k_classsum<<<CF, 256>>>(xn_f, srt_f, off_f, cnt_f, sum_f);
    k_classsum<<<CR, 256>>>(xn_r, srt_r, off_r, cnt_r, sum_r);
    k_proto<<<CF, 256>>>(sum_f, pf, cnt_f, pb_f);
    k_proto<<<CR, 256>>>(sum_r, pr, cnt_r, pb_r);
    k_loss_tc<CF><<<NB / 128, 256, SMEM_LOSS>>>(xn_f, pb_f, tlab, ls_f, lc_f);
    k_loss_tc<CR><<<NR / 128, 256, SMEM_LOSS>>>(xn_r, pb_r, nlab, ls_r, lc_r);
    k_final<<<1, 1024>>>(out);
}

// round 9
// speedup vs baseline: 3.1436x; 1.0370x over previous
#include <cuda_runtime.h>
#include <cuda_bf16.h>
#include <math.h>
#include <stdint.h>

#define D   256
#define NB  65536
#define NR  131072
#define CF  128
#define CR  512
#define EPSN  1e-12f
// (1/T) * log2(e)
#define SC2 4.8089834696296117f
#define LN2 0.6931471805599453f

// ---------------- scratch (static device globals; no runtime alloc) ----------------
__device__ int   g_cnt_f[CF];
__device__ int   g_cnt_r[CR];
__device__ int   g_off_f[CF];
__device__ int   g_off_r[CR];
__device__ int   g_cur_f[CF];
__device__ int   g_cur_r[CR];
__device__ int   g_srt_f[NB];
__device__ int   g_srt_r[NR];
__device__ float g_sum_f[CF*D];
__device__ float g_sum_r[CR*D];
__device__ __nv_bfloat16 g_pb_f[CF*D];   // updated prototypes, bf16
__device__ __nv_bfloat16 g_pb_r[CR*D];
__device__ float g_ls_f[NB/128];
__device__ float g_lc_f[NB/128];
__device__ float g_ls_r[NR/128];
__device__ float g_lc_r[NR/128];

__device__ __forceinline__ uint32_t smem_u32(const void* p) {
    uint32_t a;
    asm("{ .reg .u64 t; cvta.to.shared.u64 t, %1; cvt.u32.u64 %0, t; }" : "=r"(a) : "l"(p));
    return a;
}
__device__ __forceinline__ uint32_t pack_bf2(float x, float y) {
    __nv_bfloat162 v = __floats2bfloat162_rn(x, y);
    return *reinterpret_cast<uint32_t*>(&v);
}
__device__ __forceinline__ float ex2f_fast(float x) {
    float r; asm("ex2.approx.f32 %0, %1;" : "=f"(r) : "f"(x)); return r;
}
__device__ __forceinline__ float lg2f_fast(float x) {
    float r; asm("lg2.approx.f32 %0, %1;" : "=f"(r) : "f"(x)); return r;
}

#define LDSM_X4(r, addr) \
    asm volatile("ldmatrix.sync.aligned.m8n8.x4.shared.b16 {%0,%1,%2,%3}, [%4];" \
        : "=r"((r)[0]), "=r"((r)[1]), "=r"((r)[2]), "=r"((r)[3]) : "r"(addr))

__device__ __forceinline__ void mma_bf16(float* c, const uint32_t* a, const uint32_t* b) {
    asm volatile(
        "mma.sync.aligned.m16n8k16.row.col.f32.bf16.bf16.f32 "
        "{%0,%1,%2,%3}, {%4,%5,%6,%7}, {%8,%9}, {%0,%1,%2,%3};"
        : "+f"(c[0]), "+f"(c[1]), "+f"(c[2]), "+f"(c[3])
        : "r"(a[0]), "r"(a[1]), "r"(a[2]), "r"(a[3]), "r"(b[0]), "r"(b[1]));
}

#define CP_COMMIT() asm volatile("cp.async.commit_group;" ::: "memory")
#define CP_WAIT0()  asm volatile("cp.async.wait_group 0;" ::: "memory")

// ---------------- zero per-call counters ----------------
__global__ void k_zero() {
    int t = threadIdx.x;
    if (t < CF) g_cnt_f[t] = 0;
    if (t < CR) g_cnt_r[t] = 0;
}

// ---------------- fused label histogram (blocks 0..255 fti, 256..511 rcl) ----------------
__global__ void k_hist2(const int* __restrict__ tlab, const int* __restrict__ nlab) {
    __shared__ int sh[CR];
    bool fti = blockIdx.x < 256;
    const int* lab = fti ? tlab : nlab;
    int n   = fti ? NB : NR;
    int C   = fti ? CF : CR;
    int* cnt = fti ? g_cnt_f : g_cnt_r;
    int b   = fti ? blockIdx.x : blockIdx.x - 256;
    for (int i = threadIdx.x; i < C; i += blockDim.x) sh[i] = 0;
    __syncthreads();
    for (int i = b * blockDim.x + threadIdx.x; i < n; i += 256 * blockDim.x) {
        int l = lab[i];
        if (l >= 0) atomicAdd(&sh[l], 1);
    }
    __syncthreads();
    for (int i = threadIdx.x; i < C; i += blockDim.x)
        if (sh[i]) atomicAdd(&cnt[i], sh[i]);
}

// ---------------- exclusive scan of both count arrays ----------------
__global__ void k_scan() {
    __shared__ int sh[CR];
    int t = threadIdx.x;
    if (t < CF) sh[t] = g_cnt_f[t];
    __syncthreads();
    for (int o = 1; o < CF; o <<= 1) {
        int v = (t < CF && t >= o) ? sh[t - o] : 0;
        __syncthreads();
        if (t < CF) sh[t] += v;
        __syncthreads();
    }
    if (t < CF) { int e = sh[t] - g_cnt_f[t]; g_off_f[t] = e; g_cur_f[t] = e; }
    __syncthreads();
    if (t < CR) sh[t] = g_cnt_r[t];
    __syncthreads();
    for (int o = 1; o < CR; o <<= 1) {
        int v = (t < CR && t >= o) ? sh[t - o] : 0;
        __syncthreads();
        if (t < CR) sh[t] += v;
        __syncthreads();
    }
    if (t < CR) { int e = sh[t] - g_cnt_r[t]; g_off_r[t] = e; g_cur_r[t] = e; }
}

// ---------------- fused scatter ----------------
__global__ void k_scatter2(const int* __restrict__ tlab, const int* __restrict__ nlab) {
    int i = blockIdx.x * blockDim.x + threadIdx.x;
    if (i < NB) {
        int l = tlab[i];
        if (l >= 0) g_srt_f[atomicAdd(&g_cur_f[l], 1)] = i;
    } else {
        int j = i - NB;
        int l = nlab[j];
        if (l >= 0) g_srt_r[atomicAdd(&g_cur_r[l], 1)] = j;
    }
}

// ---------------- fused per-class normalized-row sum (fp32, warp-per-row) ----------------
__global__ __launch_bounds__(256) void k_classsum2(
    const float* __restrict__ Xf, const float* __restrict__ Xr)
{
    __shared__ float sh[8][256];
    bool fti = blockIdx.x < CF;
    int c = fti ? blockIdx.x : blockIdx.x - CF;
    const float* x   = fti ? Xf : Xr;
    const int*   srt = fti ? g_srt_f : g_srt_r;
    int s0 = fti ? g_off_f[c] : g_off_r[c];
    int n  = fti ? g_cnt_f[c] : g_cnt_r[c];
    float* sums = (fti ? g_sum_f : g_sum_r) + c * D;

    int tid = threadIdx.x, w = tid >> 5, lane = tid & 31;
    float a0 = 0.f, a1 = 0.f, a2 = 0.f, a3 = 0.f;
    float b0 = 0.f, b1 = 0.f, b2 = 0.f, b3 = 0.f;
    for (int r = w; r < n; r += 8) {
        int idx = srt[s0 + r];
        const float4* row = (const float4*)(x + (size_t)idx * D);
        float4 fa = row[lane];
        float4 fb = row[32 + lane];
        float ss = fa.x*fa.x + fa.y*fa.y + fa.z*fa.z + fa.w*fa.w
                 + fb.x*fb.x + fb.y*fb.y + fb.z*fb.z + fb.w*fb.w;
        #pragma unroll
        for (int o = 16; o; o >>= 1) ss += __shfl_xor_sync(0xffffffffu, ss, o);
        float inv = 1.0f / fmaxf(sqrtf(ss), EPSN);
        a0 += fa.x * inv; a1 += fa.y * inv; a2 += fa.z * inv; a3 += fa.w * inv;
        b0 += fb.x * inv; b1 += fb.y * inv; b2 += fb.z * inv; b3 += fb.w * inv;
    }
    sh[w][lane * 4 + 0] = a0; sh[w][lane * 4 + 1] = a1;
    sh[w][lane * 4 + 2] = a2; sh[w][lane * 4 + 3] = a3;
    sh[w][128 + lane * 4 + 0] = b0; sh[w][128 + lane * 4 + 1] = b1;
    sh[w][128 + lane * 4 + 2] = b2; sh[w][128 + lane * 4 + 3] = b3;
    __syncthreads();
    float s = 0.f;
    #pragma unroll
    for (int ww = 0; ww < 8; ww++) s += sh[ww][tid];
    sums[tid] = s;
}

// ---------------- fused prototype EMA update -> bf16 ----------------
__global__ __launch_bounds__(256) void k_proto2(
    const float* __restrict__ pf, const float* __restrict__ pr)
{
    __shared__ float sh[256];
    bool fti = blockIdx.x < CF;
    int c = fti ? blockIdx.x : blockIdx.x - CF;
    int n = fti ? g_cnt_f[c] : g_cnt_r[c];
    const float* sums = (fti ? g_sum_f : g_sum_r) + c * D;
    const float* pin  = (fti ? pf : pr) + c * D;
    __nv_bfloat16* pout = (fti ? g_pb_f : g_pb_r) + c * D;

    int t = threadIdx.x;
    float mv = sums[t] / fmaxf((float)n, 1.f);
    sh[t] = mv * mv;
    __syncthreads();
    #pragma unroll
    for (int o = 128; o; o >>= 1) { if (t < o) sh[t] += sh[t + o]; __syncthreads(); }
    float nm = fmaxf(sqrtf(sh[0]), EPSN);
    __syncthreads();
    mv = mv / nm;
    float p = pin[t];
    float q = 0.5f * p + 0.5f * mv;
    sh[t] = q * q;
    __syncthreads();
    #pragma unroll
    for (int o = 128; o; o >>= 1) { if (t < o) sh[t] += sh[t + o]; __syncthreads(); }
    float nq = fmaxf(sqrtf(sh[0]), EPSN);
    pout[t] = __float2bfloat16((n > 0) ? q / nq : p);
}

// ---------------- fused single-bf16 mma.sync GEMM + softmax CE ----------------
#define A_OFF   4096
#define B0_OFF  71680
#define BBUF    67584
#define SMEM_LOSS 206848
#define NBLK_F (NB/128)

__device__ __forceinline__ void prefetch_B(uint32_t sbu, uint32_t dstOff,
                                           const __nv_bfloat16* __restrict__ P,
                                           int c0, int tid) {
    #pragma unroll
    for (int i = 0; i < 16; i++) {
        int ch = tid + i * 256;
        int r  = ch >> 5;
        int c8 = (ch & 31) * 8;
        uint32_t dst = sbu + dstOff + (uint32_t)(r * 528 + c8 * 2);
        const void* src = P + (size_t)(c0 + r) * D + c8;
        asm volatile("cp.async.cg.shared.global [%0], [%1], 16;" :: "r"(dst), "l"(src));
    }
}

__global__ __launch_bounds__(256, 1)
void k_loss_tc(const float* __restrict__ Xf, const float* __restrict__ Xr,
               const int* __restrict__ tlab, const int* __restrict__ nlab)
{
    extern __shared__ char smem[];
    int*   lab_sm   = (int*)(smem + 0);
    float* scale_sm = (float*)(smem + 512);
    float* rs_sm    = (float*)(smem + 1024);
    float* tg_sm    = (float*)(smem + 2048);
    float* red_s    = (float*)(smem + 3072);
    float* red_c    = (float*)(smem + 3104);

    const bool fti = blockIdx.x < NBLK_F;
    const int  bid = fti ? blockIdx.x : blockIdx.x - NBLK_F;
    const float* X = fti ? Xf : Xr;
    const __nv_bfloat16* Pb = fti ? g_pb_f : g_pb_r;
    const int* lab = fti ? tlab : nlab;
    float* lsum = fti ? g_ls_f : g_ls_r;
    float* lcnt = fti ? g_lc_f : g_lc_r;
    const int NCH = fti ? (CF / 128) : (CR / 128);

    const int tid  = threadIdx.x;
    const int wid  = tid >> 5;
    const int lane = tid & 31;
    const int wr   = wid & 3;
    const int wc   = wid >> 2;
    const int row0 = bid * 128;
    const uint32_t sbu = smem_u32(smem);

    if (tid < 128) lab_sm[tid] = lab[row0 + tid];

    // ---- A: fp32 load, row sumsq via warp reduce, store unnormalized bf16 ----
    #pragma unroll
    for (int i = 0; i < 16; i++) {
        int r  = i * 8 + wid;
        int c8 = lane * 8;
        const float* src = X + (size_t)(row0 + r) * D + c8;
        float4 v0 = *(const float4*)src;
        float4 v1 = *(const float4*)(src + 4);
        float ss = v0.x*v0.x + v0.y*v0.y + v0.z*v0.z + v0.w*v0.w
                 + v1.x*v1.x + v1.y*v1.y + v1.z*v1.z + v1.w*v1.w;
        #pragma unroll
        for (int o = 16; o; o >>= 1) ss += __shfl_xor_sync(0xffffffffu, ss, o);
        if (lane == 0) scale_sm[r] = SC2 / fmaxf(sqrtf(ss), EPSN);
        uint4 hv = make_uint4(pack_bf2(v0.x, v0.y), pack_bf2(v0.z, v0.w),
                              pack_bf2(v1.x, v1.y), pack_bf2(v1.z, v1.w));
        *(uint4*)(smem + A_OFF + r * 528 + c8 * 2) = hv;
    }

    prefetch_B(sbu, B0_OFF, Pb, 0, tid);
    CP_COMMIT();
    CP_WAIT0();
    __syncthreads();

    int lb4[4]; float sc4[4];
    #pragma unroll
    for (int mt = 0; mt < 2; mt++)
        #pragma unroll
        for (int h = 0; h < 2; h++) {
            int r = wr * 32 + mt * 16 + (lane >> 2) + h * 8;
            lb4[mt * 2 + h] = lab_sm[r];
            sc4[mt * 2 + h] = scale_sm[r];
        }

    const uint32_t aBase = sbu + A_OFF
        + (uint32_t)(wr * 32 + (lane & 15)) * 528 + (uint32_t)(lane >> 4) * 16;
    const uint32_t bB0 = sbu + B0_OFF
        + (uint32_t)(wc * 64 + (lane & 7) + ((lane >> 4) & 1) * 8) * 528
        + (uint32_t)((lane >> 3) & 1) * 16;

    float ssum[4] = {0.f, 0.f, 0.f, 0.f};
    float tgt[4]  = {0.f, 0.f, 0.f, 0.f};

    for (int c = 0; c < NCH; c++) {
        if (c) { CP_WAIT0(); __syncthreads(); }
        if (c + 1 < NCH) {
            prefetch_B(sbu, B0_OFF + (uint32_t)((c + 1) & 1) * BBUF, Pb, (c + 1) * 128, tid);
            CP_COMMIT();
        }
        const uint32_t bBase = bB0 + (uint32_t)(c & 1) * BBUF;

        float acc[2][8][4];
        #pragma unroll
        for (int mt = 0; mt < 2; mt++)
            #pragma unroll
            for (int nt = 0; nt < 8; nt++)
                #pragma unroll
                for (int e = 0; e < 4; e++) acc[mt][nt][e] = 0.f;

        #pragma unroll
        for (int k16 = 0; k16 < 16; k16++) {
            uint32_t aoff = (uint32_t)k16 * 32;
            uint32_t ah0[4], ah1[4];
            LDSM_X4(ah0, aBase + aoff);
            LDSM_X4(ah1, aBase + 8448 + aoff);
            #pragma unroll
            for (int ntp = 0; ntp < 4; ntp++) {
                uint32_t bh[4];
                LDSM_X4(bh, bBase + (uint32_t)ntp * 8448 + aoff);
                mma_bf16(acc[0][ntp*2],   ah0, bh);
                mma_bf16(acc[1][ntp*2],   ah1, bh);
                mma_bf16(acc[0][ntp*2+1], ah0, bh + 2);
                mma_bf16(acc[1][ntp*2+1], ah1, bh + 2);
            }
        }

        int c0 = c * 128;
        #pragma unroll
        for (int mt = 0; mt < 2; mt++)
            #pragma unroll
            for (int nt = 0; nt < 8; nt++) {
                int colb = c0 + wc * 64 + nt * 8 + (lane & 3) * 2;
                float l0 = acc[mt][nt][0] * sc4[mt*2];
                float l1 = acc[mt][nt][1] * sc4[mt*2];
                float l2 = acc[mt][nt][2] * sc4[mt*2+1];
                float l3 = acc[mt][nt][3] * sc4[mt*2+1];
                ssum[mt*2]   += ex2f_fast(l0) + ex2f_fast(l1);
                ssum[mt*2+1] += ex2f_fast(l2) + ex2f_fast(l3);
                if (lb4[mt*2]   == colb)     tgt[mt*2]   = l0;
                if (lb4[mt*2]   == colb + 1) tgt[mt*2]   = l1;
                if (lb4[mt*2+1] == colb)     tgt[mt*2+1] = l2;
                if (lb4[mt*2+1] == colb + 1) tgt[mt*2+1] = l3;
            }
    }

    #pragma unroll
    for (int i = 0; i < 4; i++) {
        ssum[i] += __shfl_xor_sync(0xffffffffu, ssum[i], 1);
        ssum[i] += __shfl_xor_sync(0xffffffffu, ssum[i], 2);
        tgt[i]  += __shfl_xor_sync(0xffffffffu, tgt[i], 1);
        tgt[i]  += __shfl_xor_sync(0xffffffffu, tgt[i], 2);
    }
    if ((lane & 3) == 0) {
        #pragma unroll
        for (int i = 0; i < 4; i++) {
            int r = wr * 32 + (i >> 1) * 16 + (lane >> 2) + (i & 1) * 8;
            rs_sm[r * 2 + wc] = ssum[i];
            tg_sm[r * 2 + wc] = tgt[i];
        }
    }
    __syncthreads();

    float v = 0.f, cn = 0.f;
    if (tid < 128) {
        int lb = lab_sm[tid];
        if (lb >= 0) {
            float S  = rs_sm[tid * 2] + rs_sm[tid * 2 + 1];
            float T2 = tg_sm[tid * 2] + tg_sm[tid * 2 + 1];
            v  = LN2 * (lg2f_fast(S) - T2);
            cn = 1.f;
        }
    }
    #pragma unroll
    for (int o = 16; o; o >>= 1) {
        v  += __shfl_xor_sync(0xffffffffu, v, o);
        cn += __shfl_xor_sync(0xffffffffu, cn, o);
    }
    if (lane == 0) { red_s[wid] = v; red_c[wid] = cn; }
    __syncthreads();
    if (tid == 0) {
        lsum[bid] = red_s[0] + red_s[1] + red_s[2] + red_s[3];
        lcnt[bid] = red_c[0] + red_c[1] + red_c[2] + red_c[3];
    }
}

// ---------------- final reduction of per-block partials ----------------
__global__ void k_final(float* __restrict__ out) {
    __shared__ float sh[1024];
    int t = threadIdx.x;
    float v;

    v = (t < NB / 128) ? g_ls_f[t] : 0.f;
    sh[t] = v; __syncthreads();
    #pragma unroll
    for (int o = 512; o; o >>= 1) { if (t < o) sh[t] += sh[t + o]; __syncthreads(); }
    float sf = sh[0]; __syncthreads();

    v = (t < NB / 128) ? g_lc_f[t] : 0.f;
    sh[t] = v; __syncthreads();
    #pragma unroll
    for (int o = 512; o; o >>= 1) { if (t < o) sh[t] += sh[t + o]; __syncthreads(); }
    float cf = sh[0]; __syncthreads();

    v = g_ls_r[t];
    sh[t] = v; __syncthreads();
    #pragma unroll
    for (int o = 512; o; o >>= 1) { if (t < o) sh[t] += sh[t + o]; __syncthreads(); }
    float sr = sh[0]; __syncthreads();

    v = g_lc_r[t];
    sh[t] = v; __syncthreads();
    #pragma unroll
    for (int o = 512; o; o >>= 1) { if (t < o) sh[t] += sh[t + o]; __syncthreads(); }
    float cr = sh[0];

    if (t == 0) {
        out[0] = sf / fmaxf(cf, 1.f);
        out[1] = sr / fmaxf(cr, 1.f);
    }
}

// ---------------- host launcher (graph-capturable, allocation-free) ----------------
extern "C" void kernel_launch(void* const* d_in, const int* in_sizes, int n_in,
                              void* d_out, int out_size) {
    (void)in_sizes; (void)n_in; (void)out_size;
    const float* f_fti = (const float*)d_in[0];
    const float* e_rcl = (const float*)d_in[1];
    const int*   tlab  = (const int*)d_in[2];
    const int*   nlab  = (const int*)d_in[3];
    const float* pf    = (const float*)d_in[4];
    const float* pr    = (const float*)d_in[5];
    float* out = (float*)d_out;

    cudaFuncSetAttribute(k_loss_tc, cudaFuncAttributeMaxDynamicSharedMemorySize, SMEM_LOSS);

    k_zero<<<1, 512>>>();
    k_hist2<<<512, 256>>>(tlab, nlab);
    k_scan<<<1, 512>>>();
    k_scatter2<<<(NB + NR) / 256, 256>>>(tlab, nlab);
    k_classsum2<<<CF + CR, 256>>>(f_fti, e_rcl);
    k_proto2<<<CF + CR, 256>>>(pf, pr);
    k_loss_tc<<<NB / 128 + NR / 128, 256, SMEM_LOSS>>>(f_fti, e_rcl, tlab, nlab);
    k_final<<<1, 1024>>>(out);
}

// round 10
// speedup vs baseline: 3.6569x; 1.1633x over previous
#include <cuda_runtime.h>
#include <cuda_bf16.h>
#include <math.h>
#include <stdint.h>

#define D   256
#define NB  65536
#define NR  131072
#define CF  128
#define CR  512
#define EPSN  1e-12f
// (1/T) * log2(e)
#define SC2 4.8089834696296117f
#define LN2 0.6931471805599453f

// ---------------- scratch (static device globals; no runtime alloc) ----------------
__device__ int   g_cnt_f[CF];
__device__ int   g_cnt_r[CR];
__device__ int   g_off_f[CF];
__device__ int   g_off_r[CR];
__device__ int   g_cur_f[CF];
__device__ int   g_cur_r[CR];
__device__ int   g_srt_f[NB];
__device__ int   g_srt_r[NR];
__device__ float g_sum_f[CF*D];
__device__ float g_sum_r[CR*D];
__device__ int8_t g_pbq_f[CF*D];   // updated prototypes, int8
__device__ int8_t g_pbq_r[CR*D];
__device__ float  g_pbs_f[CF];     // per-class dequant scale (max/127)
__device__ float  g_pbs_r[CR];
__device__ float g_ls_f[NB/128];
__device__ float g_lc_f[NB/128];
__device__ float g_ls_r[NR/128];
__device__ float g_lc_r[NR/128];

__device__ __forceinline__ uint32_t smem_u32(const void* p) {
    uint32_t a;
    asm("{ .reg .u64 t; cvta.to.shared.u64 t, %1; cvt.u32.u64 %0, t; }" : "=r"(a) : "l"(p));
    return a;
}
__device__ __forceinline__ float ex2f_fast(float x) {
    float r; asm("ex2.approx.f32 %0, %1;" : "=f"(r) : "f"(x)); return r;
}
__device__ __forceinline__ float lg2f_fast(float x) {
    float r; asm("lg2.approx.f32 %0, %1;" : "=f"(r) : "f"(x)); return r;
}

#define LDSM_X4(r, addr) \
    asm volatile("ldmatrix.sync.aligned.m8n8.x4.shared.b16 {%0,%1,%2,%3}, [%4];" \
        : "=r"((r)[0]), "=r"((r)[1]), "=r"((r)[2]), "=r"((r)[3]) : "r"(addr))

// int8 MMA: D(s32) += A(s8,16x32) * B(s8,8x32)^T — 2x MACs/instr vs bf16 k16
__device__ __forceinline__ void mma_s8(int* c, const uint32_t* a, const uint32_t* b) {
    asm volatile(
        "mma.sync.aligned.m16n8k32.row.col.s32.s8.s8.s32 "
        "{%0,%1,%2,%3}, {%4,%5,%6,%7}, {%8,%9}, {%0,%1,%2,%3};"
        : "+r"(c[0]), "+r"(c[1]), "+r"(c[2]), "+r"(c[3])
        : "r"(a[0]), "r"(a[1]), "r"(a[2]), "r"(a[3]), "r"(b[0]), "r"(b[1]));
}

#define CP_COMMIT() asm volatile("cp.async.commit_group;" ::: "memory")
#define CP_WAIT0()  asm volatile("cp.async.wait_group 0;" ::: "memory")

// ---------------- zero per-call counters ----------------
__global__ void k_zero() {
    int t = threadIdx.x;
    if (t < CF) g_cnt_f[t] = 0;
    if (t < CR) g_cnt_r[t] = 0;
}

// ---------------- fused label histogram ----------------
__global__ void k_hist2(const int* __restrict__ tlab, const int* __restrict__ nlab) {
    __shared__ int sh[CR];
    bool fti = blockIdx.x < 256;
    const int* lab = fti ? tlab : nlab;
    int n   = fti ? NB : NR;
    int C   = fti ? CF : CR;
    int* cnt = fti ? g_cnt_f : g_cnt_r;
    int b   = fti ? blockIdx.x : blockIdx.x - 256;
    for (int i = threadIdx.x; i < C; i += blockDim.x) sh[i] = 0;
    __syncthreads();
    for (int i = b * blockDim.x + threadIdx.x; i < n; i += 256 * blockDim.x) {
        int l = lab[i];
        if (l >= 0) atomicAdd(&sh[l], 1);
    }
    __syncthreads();
    for (int i = threadIdx.x; i < C; i += blockDim.x)
        if (sh[i]) atomicAdd(&cnt[i], sh[i]);
}

// ---------------- exclusive scan ----------------
__global__ void k_scan() {
    __shared__ int sh[CR];
    int t = threadIdx.x;
    if (t < CF) sh[t] = g_cnt_f[t];
    __syncthreads();
    for (int o = 1; o < CF; o <<= 1) {
        int v = (t < CF && t >= o) ? sh[t - o] : 0;
        __syncthreads();
        if (t < CF) sh[t] += v;
        __syncthreads();
    }
    if (t < CF) { int e = sh[t] - g_cnt_f[t]; g_off_f[t] = e; g_cur_f[t] = e; }
    __syncthreads();
    if (t < CR) sh[t] = g_cnt_r[t];
    __syncthreads();
    for (int o = 1; o < CR; o <<= 1) {
        int v = (t < CR && t >= o) ? sh[t - o] : 0;
        __syncthreads();
        if (t < CR) sh[t] += v;
        __syncthreads();
    }
    if (t < CR) { int e = sh[t] - g_cnt_r[t]; g_off_r[t] = e; g_cur_r[t] = e; }
}

// ---------------- fused scatter ----------------
__global__ void k_scatter2(const int* __restrict__ tlab, const int* __restrict__ nlab) {
    int i = blockIdx.x * blockDim.x + threadIdx.x;
    if (i < NB) {
        int l = tlab[i];
        if (l >= 0) g_srt_f[atomicAdd(&g_cur_f[l], 1)] = i;
    } else {
        int j = i - NB;
        int l = nlab[j];
        if (l >= 0) g_srt_r[atomicAdd(&g_cur_r[l], 1)] = j;
    }
}

// ---------------- fused per-class normalized-row sum ----------------
__global__ __launch_bounds__(256) void k_classsum2(
    const float* __restrict__ Xf, const float* __restrict__ Xr)
{
    __shared__ float sh[8][256];
    bool fti = blockIdx.x < CF;
    int c = fti ? blockIdx.x : blockIdx.x - CF;
    const float* x   = fti ? Xf : Xr;
    const int*   srt = fti ? g_srt_f : g_srt_r;
    int s0 = fti ? g_off_f[c] : g_off_r[c];
    int n  = fti ? g_cnt_f[c] : g_cnt_r[c];
    float* sums = (fti ? g_sum_f : g_sum_r) + c * D;

    int tid = threadIdx.x, w = tid >> 5, lane = tid & 31;
    float a0 = 0.f, a1 = 0.f, a2 = 0.f, a3 = 0.f;
    float b0 = 0.f, b1 = 0.f, b2 = 0.f, b3 = 0.f;
    for (int r = w; r < n; r += 8) {
        int idx = srt[s0 + r];
        const float4* row = (const float4*)(x + (size_t)idx * D);
        float4 fa = row[lane];
        float4 fb = row[32 + lane];
        float ss = fa.x*fa.x + fa.y*fa.y + fa.z*fa.z + fa.w*fa.w
                 + fb.x*fb.x + fb.y*fb.y + fb.z*fb.z + fb.w*fb.w;
        #pragma unroll
        for (int o = 16; o; o >>= 1) ss += __shfl_xor_sync(0xffffffffu, ss, o);
        float inv = 1.0f / fmaxf(sqrtf(ss), EPSN);
        a0 += fa.x * inv; a1 += fa.y * inv; a2 += fa.z * inv; a3 += fa.w * inv;
        b0 += fb.x * inv; b1 += fb.y * inv; b2 += fb.z * inv; b3 += fb.w * inv;
    }
    sh[w][lane * 4 + 0] = a0; sh[w][lane * 4 + 1] = a1;
    sh[w][lane * 4 + 2] = a2; sh[w][lane * 4 + 3] = a3;
    sh[w][128 + lane * 4 + 0] = b0; sh[w][128 + lane * 4 + 1] = b1;
    sh[w][128 + lane * 4 + 2] = b2; sh[w][128 + lane * 4 + 3] = b3;
    __syncthreads();
    float s = 0.f;
    #pragma unroll
    for (int ww = 0; ww < 8; ww++) s += sh[ww][tid];
    sums[tid] = s;
}

// ---------------- fused prototype EMA update -> int8 + per-class scale ----------------
__global__ __launch_bounds__(256) void k_proto2(
    const float* __restrict__ pf, const float* __restrict__ pr)
{
    __shared__ float sh[256];
    bool fti = blockIdx.x < CF;
    int c = fti ? blockIdx.x : blockIdx.x - CF;
    int n = fti ? g_cnt_f[c] : g_cnt_r[c];
    const float* sums = (fti ? g_sum_f : g_sum_r) + c * D;
    const float* pin  = (fti ? pf : pr) + c * D;
    int8_t* pout = (fti ? g_pbq_f : g_pbq_r) + c * D;
    float*  psc  = fti ? g_pbs_f : g_pbs_r;

    int t = threadIdx.x;
    float mv = sums[t] / fmaxf((float)n, 1.f);
    sh[t] = mv * mv;
    __syncthreads();
    #pragma unroll
    for (int o = 128; o; o >>= 1) { if (t < o) sh[t] += sh[t + o]; __syncthreads(); }
    float nm = fmaxf(sqrtf(sh[0]), EPSN);
    __syncthreads();
    mv = mv / nm;
    float p = pin[t];
    float q = 0.5f * p + 0.5f * mv;
    sh[t] = q * q;
    __syncthreads();
    #pragma unroll
    for (int o = 128; o; o >>= 1) { if (t < o) sh[t] += sh[t + o]; __syncthreads(); }
    float nq = fmaxf(sqrtf(sh[0]), EPSN);
    float val = (n > 0) ? q / nq : p;
    __syncthreads();
    // per-class max|val| for int8 quantization
    sh[t] = fabsf(val);
    __syncthreads();
    #pragma unroll
    for (int o = 128; o; o >>= 1) { if (t < o) sh[t] = fmaxf(sh[t], sh[t + o]); __syncthreads(); }
    float m = fmaxf(sh[0], 1e-30f);
    int qv = __float2int_rn(val * (127.f / m));
    qv = max(-127, min(127, qv));
    pout[t] = (int8_t)qv;
    if (t == 0) psc[c] = m * (1.f / 127.f);
}

// ---------------- int8 mma.sync fused GEMM + softmax CE ----------------
// logit*log2e/T = dot_s32 * [SC2*inv*mxA/127]_row * [mxB/127]_col.
// A: fp32 load -> row sumsq+max via shfl -> int8 smem (stride 272B, 17x16B
// units: conflict-free ldmatrix). B int8 chunk double-buffered via cp.async.
// s8-k32 fragments are byte-identical to bf16-k16 under ldmatrix.b16.
// smem: 0 lab | 512 scale | 1024 rs | 2048 tg | 3072 red | 3200 scb[512]
//       5376 A(34816) | 40192 B0(34816) | 75008 B1(34816) -> 109824 (2 CTA/SM)
#define A_OFF   5376
#define B0_OFF  40192
#define BBUF    34816
#define SMEM_LOSS 109824
#define NBLK_F (NB/128)

__device__ __forceinline__ void prefetch_B(uint32_t sbu, uint32_t dstOff,
                                           const int8_t* __restrict__ P,
                                           int c0, int tid) {
    #pragma unroll
    for (int i = 0; i < 8; i++) {
        int ch = tid + i * 256;           // 2048 chunks of 16 bytes
        int r  = ch >> 4;                 // class row 0..127
        int c16 = (ch & 15) * 16;         // k byte 0..240
        uint32_t dst = sbu + dstOff + (uint32_t)(r * 272 + c16);
        const void* src = P + (size_t)(c0 + r) * D + c16;
        asm volatile("cp.async.cg.shared.global [%0], [%1], 16;" :: "r"(dst), "l"(src));
    }
}

__global__ __launch_bounds__(256)
void k_loss_tc(const float* __restrict__ Xf, const float* __restrict__ Xr,
               const int* __restrict__ tlab, const int* __restrict__ nlab)
{
    extern __shared__ char smem[];
    int*   lab_sm   = (int*)(smem + 0);
    float* scale_sm = (float*)(smem + 512);
    float* rs_sm    = (float*)(smem + 1024);
    float* tg_sm    = (float*)(smem + 2048);
    float* red_s    = (float*)(smem + 3072);
    float* red_c    = (float*)(smem + 3104);
    float* scb_sm   = (float*)(smem + 3200);

    const bool fti = blockIdx.x < NBLK_F;
    const int  bid = fti ? blockIdx.x : blockIdx.x - NBLK_F;
    const float* X = fti ? Xf : Xr;
    const int8_t* Pq = fti ? g_pbq_f : g_pbq_r;
    const float*  Ps = fti ? g_pbs_f : g_pbs_r;
    const int* lab = fti ? tlab : nlab;
    float* lsum = fti ? g_ls_f : g_ls_r;
    float* lcnt = fti ? g_lc_f : g_lc_r;
    const int NCH = fti ? (CF / 128) : (CR / 128);

    const int tid  = threadIdx.x;
    const int wid  = tid >> 5;
    const int lane = tid & 31;
    const int wr   = wid & 3;
    const int wc   = wid >> 2;
    const int row0 = bid * 128;
    const uint32_t sbu = smem_u32(smem);

    if (tid < 128) lab_sm[tid] = lab[row0 + tid];
    for (int i = tid; i < NCH * 128; i += 256) scb_sm[i] = Ps[i];

    // ---- A: fp32 load, row sumsq+max via warp reduce, int8 quant to smem ----
    #pragma unroll
    for (int i = 0; i < 16; i++) {
        int r  = i * 8 + wid;             // warp owns full row r this iteration
        const float* src = X + (size_t)(row0 + r) * D + lane * 8;
        float4 v0 = *(const float4*)src;
        float4 v1 = *(const float4*)(src + 4);
        float ss = v0.x*v0.x + v0.y*v0.y + v0.z*v0.z + v0.w*v0.w
                 + v1.x*v1.x + v1.y*v1.y + v1.z*v1.z + v1.w*v1.w;
        float mx = fmaxf(fmaxf(fmaxf(fabsf(v0.x), fabsf(v0.y)), fmaxf(fabsf(v0.z), fabsf(v0.w))),
                         fmaxf(fmaxf(fabsf(v1.x), fabsf(v1.y)), fmaxf(fabsf(v1.z), fabsf(v1.w))));
        #pragma unroll
        for (int o = 16; o; o >>= 1) {
            ss += __shfl_xor_sync(0xffffffffu, ss, o);
            mx  = fmaxf(mx, __shfl_xor_sync(0xffffffffu, mx, o));
        }
        mx = fmaxf(mx, 1e-30f);
        float inv = 1.0f / fmaxf(sqrtf(ss), EPSN);
        if (lane == 0) scale_sm[r] = SC2 * inv * mx * (1.f / 127.f);
        float qs = 127.f / mx;
        int q0 = __float2int_rn(v0.x * qs), q1 = __float2int_rn(v0.y * qs);
        int q2 = __float2int_rn(v0.z * qs), q3 = __float2int_rn(v0.w * qs);
        int q4 = __float2int_rn(v1.x * qs), q5 = __float2int_rn(v1.y * qs);
        int q6 = __float2int_rn(v1.z * qs), q7 = __float2int_rn(v1.w * qs);
        uint32_t p0 = (q0 & 0xFF) | ((q1 & 0xFF) << 8) | ((q2 & 0xFF) << 16) | ((q3 & 0xFF) << 24);
        uint32_t p1 = (q4 & 0xFF) | ((q5 & 0xFF) << 8) | ((q6 & 0xFF) << 16) | ((q7 & 0xFF) << 24);
        *(uint2*)(smem + A_OFF + r * 272 + lane * 8) = make_uint2(p0, p1);
    }

    prefetch_B(sbu, B0_OFF, Pq, 0, tid);
    CP_COMMIT();
    CP_WAIT0();
    __syncthreads();

    int lb4[4]; float sc4[4];
    #pragma unroll
    for (int mt = 0; mt < 2; mt++)
        #pragma unroll
        for (int h = 0; h < 2; h++) {
            int r = wr * 32 + mt * 16 + (lane >> 2) + h * 8;
            lb4[mt * 2 + h] = lab_sm[r];
            sc4[mt * 2 + h] = scale_sm[r];
        }

    const uint32_t aBase = sbu + A_OFF
        + (uint32_t)(wr * 32 + (lane & 15)) * 272 + (uint32_t)(lane >> 4) * 16;
    const uint32_t bB0 = sbu + B0_OFF
        + (uint32_t)(wc * 64 + (lane & 7) + ((lane >> 4) & 1) * 8) * 272
        + (uint32_t)((lane >> 3) & 1) * 16;

    float ssum[4] = {0.f, 0.f, 0.f, 0.f};
    float tgt[4]  = {0.f, 0.f, 0.f, 0.f};

    for (int c = 0; c < NCH; c++) {
        if (c) { CP_WAIT0(); __syncthreads(); }
        if (c + 1 < NCH) {
            prefetch_B(sbu, B0_OFF + (uint32_t)((c + 1) & 1) * BBUF, Pq, (c + 1) * 128, tid);
            CP_COMMIT();
        }
        const uint32_t bBase = bB0 + (uint32_t)(c & 1) * BBUF;

        int acc[2][8][4];
        #pragma unroll
        for (int mt = 0; mt < 2; mt++)
            #pragma unroll
            for (int nt = 0; nt < 8; nt++)
                #pragma unroll
                for (int e = 0; e < 4; e++) acc[mt][nt][e] = 0;

        #pragma unroll
        for (int k = 0; k < 8; k++) {       // 8 k32 steps = K 256
            uint32_t aoff = (uint32_t)k * 32;
            uint32_t ah0[4], ah1[4];
            LDSM_X4(ah0, aBase + aoff);
            LDSM_X4(ah1, aBase + 4352 + aoff);   // +16 rows * 272
            #pragma unroll
            for (int ntp = 0; ntp < 4; ntp++) {
                uint32_t bh[4];
                LDSM_X4(bh, bBase + (uint32_t)ntp * 4352 + aoff);
                mma_s8(acc[0][ntp*2],   ah0, bh);
                mma_s8(acc[1][ntp*2],   ah1, bh);
                mma_s8(acc[0][ntp*2+1], ah0, bh + 2);
                mma_s8(acc[1][ntp*2+1], ah1, bh + 2);
            }
        }

        int c0 = c * 128;
        #pragma unroll
        for (int nt = 0; nt < 8; nt++) {
            int colb = c0 + wc * 64 + nt * 8 + (lane & 3) * 2;
            float sb0 = scb_sm[colb];
            float sb1 = scb_sm[colb + 1];
            #pragma unroll
            for (int mt = 0; mt < 2; mt++) {
                float l0 = __int2float_rn(acc[mt][nt][0]) * sc4[mt*2]   * sb0;
                float l1 = __int2float_rn(acc[mt][nt][1]) * sc4[mt*2]   * sb1;
                float l2 = __int2float_rn(acc[mt][nt][2]) * sc4[mt*2+1] * sb0;
                float l3 = __int2float_rn(acc[mt][nt][3]) * sc4[mt*2+1] * sb1;
                ssum[mt*2]   += ex2f_fast(l0) + ex2f_fast(l1);
                ssum[mt*2+1] += ex2f_fast(l2) + ex2f_fast(l3);
                if (lb4[mt*2]   == colb)     tgt[mt*2]   = l0;
                if (lb4[mt*2]   == colb + 1) tgt[mt*2]   = l1;
                if (lb4[mt*2+1] == colb)     tgt[mt*2+1] = l2;
                if (lb4[mt*2+1] == colb + 1) tgt[mt*2+1] = l3;
            }
        }
    }

    #pragma unroll
    for (int i = 0; i < 4; i++) {
        ssum[i] += __shfl_xor_sync(0xffffffffu, ssum[i], 1);
        ssum[i] += __shfl_xor_sync(0xffffffffu, ssum[i], 2);
        tgt[i]  += __shfl_xor_sync(0xffffffffu, tgt[i], 1);
        tgt[i]  += __shfl_xor_sync(0xffffffffu, tgt[i], 2);
    }
    if ((lane & 3) == 0) {
        #pragma unroll
        for (int i = 0; i < 4; i++) {
            int r = wr * 32 + (i >> 1) * 16 + (lane >> 2) + (i & 1) * 8;
            rs_sm[r * 2 + wc] = ssum[i];
            tg_sm[r * 2 + wc] = tgt[i];
        }
    }
    __syncthreads();

    float v = 0.f, cn = 0.f;
    if (tid < 128) {
        int lb = lab_sm[tid];
        if (lb >= 0) {
            float S  = rs_sm[tid * 2] + rs_sm[tid * 2 + 1];
            float T2 = tg_sm[tid * 2] + tg_sm[tid * 2 + 1];
            v  = LN2 * (lg2f_fast(S) - T2);
            cn = 1.f;
        }
    }
    #pragma unroll
    for (int o = 16; o; o >>= 1) {
        v  += __shfl_xor_sync(0xffffffffu, v, o);
        cn += __shfl_xor_sync(0xffffffffu, cn, o);
    }
    if (lane == 0) { red_s[wid] = v; red_c[wid] = cn; }
    __syncthreads();
    if (tid == 0) {
        lsum[bid] = red_s[0] + red_s[1] + red_s[2] + red_s[3];
        lcnt[bid] = red_c[0] + red_c[1] + red_c[2] + red_c[3];
    }
}

// ---------------- final reduction of per-block partials ----------------
__global__ void k_final(float* __restrict__ out) {
    __shared__ float sh[1024];
    int t = threadIdx.x;
    float v;

    v = (t < NB / 128) ? g_ls_f[t] : 0.f;
    sh[t] = v; __syncthreads();
    #pragma unroll
    for (int o = 512; o; o >>= 1) { if (t < o) sh[t] += sh[t + o]; __syncthreads(); }
    float sf = sh[0]; __syncthreads();

    v = (t < NB / 128) ? g_lc_f[t] : 0.f;
    sh[t] = v; __syncthreads();
    #pragma unroll
    for (int o = 512; o; o >>= 1) { if (t < o) sh[t] += sh[t + o]; __syncthreads(); }
    float cf = sh[0]; __syncthreads();

    v = g_ls_r[t];
    sh[t] = v; __syncthreads();
    #pragma unroll
    for (int o = 512; o; o >>= 1) { if (t < o) sh[t] += sh[t + o]; __syncthreads(); }
    float sr = sh[0]; __syncthreads();

    v = g_lc_r[t];
    sh[t] = v; __syncthreads();
    #pragma unroll
    for (int o = 512; o; o >>= 1) { if (t < o) sh[t] += sh[t + o]; __syncthreads(); }
    float cr = sh[0];

    if (t == 0) {
        out[0] = sf / fmaxf(cf, 1.f);
        out[1] = sr / fmaxf(cr, 1.f);
    }
}

// ---------------- host launcher (graph-capturable, allocation-free) ----------------
extern "C" void kernel_launch(void* const* d_in, const int* in_sizes, int n_in,
                              void* d_out, int out_size) {
    (void)in_sizes; (void)n_in; (void)out_size;
    const float* f_fti = (const float*)d_in[0];
    const float* e_rcl = (const float*)d_in[1];
    const int*   tlab  = (const int*)d_in[2];
    const int*   nlab  = (const int*)d_in[3];
    const float* pf    = (const float*)d_in[4];
    const float* pr    = (const float*)d_in[5];
    float* out = (float*)d_out;

    cudaFuncSetAttribute(k_loss_tc, cudaFuncAttributeMaxDynamicSharedMemorySize, SMEM_LOSS);

    k_zero<<<1, 512>>>();
    k_hist2<<<512, 256>>>(tlab, nlab);
    k_scan<<<1, 512>>>();
    k_scatter2<<<(NB + NR) / 256, 256>>>(tlab, nlab);
    k_classsum2<<<CF + CR, 256>>>(f_fti, e_rcl);
    k_proto2<<<CF + CR, 256>>>(pf, pr);
    k_loss_tc<<<NB / 128 + NR / 128, 256, SMEM_LOSS>>>(f_fti, e_rcl, tlab, nlab);
    k_final<<<1, 1024>>>(out);
}

// round 12
// speedup vs baseline: 5.7934x; 1.5842x over previous
#include <cuda_runtime.h>
#include <cuda_bf16.h>
#include <math.h>
#include <stdint.h>

#define D   256
#define NB  65536
#define NR  131072
#define CF  128
#define CR  512
#define EPSN  1e-12f
// (1/T) * log2(e)
#define SC2 4.8089834696296117f
#define LN2 0.6931471805599453f

// ---------------- scratch (static device globals; no runtime alloc) ----------------
__device__ int   g_cnt_f[CF];
__device__ int   g_cnt_r[CR];
__device__ int   g_off_f[CF];
__device__ int   g_off_r[CR];
__device__ int   g_cur_f[CF];
__device__ int   g_cur_r[CR];
__device__ int   g_srt_f[NB];
__device__ int   g_srt_r[NR];
__device__ float g_sum_f[CF*D];
__device__ float g_sum_r[CR*D];
__device__ int8_t g_xq_f[NB*D];    // quantized features (written by classsum)
__device__ int8_t g_xq_r[NR*D];
__device__ float  g_xs_f[NB];      // fused per-row scale SC2*inv*mx/127
__device__ float  g_xs_r[NR];
__device__ int8_t g_pbq_f[CF*D];   // updated prototypes, int8
__device__ int8_t g_pbq_r[CR*D];
__device__ float  g_pbs_f[CF];     // per-class dequant scale (max/127)
__device__ float  g_pbs_r[CR];
__device__ float g_ls_f[NB/128];
__device__ float g_lc_f[NB/128];
__device__ float g_ls_r[NR/128];
__device__ float g_lc_r[NR/128];

__device__ __forceinline__ uint32_t smem_u32(const void* p) {
    uint32_t a;
    asm("{ .reg .u64 t; cvta.to.shared.u64 t, %1; cvt.u32.u64 %0, t; }" : "=r"(a) : "l"(p));
    return a;
}
__device__ __forceinline__ float ex2f_fast(float x) {
    float r; asm("ex2.approx.f32 %0, %1;" : "=f"(r) : "f"(x)); return r;
}
__device__ __forceinline__ float lg2f_fast(float x) {
    float r; asm("lg2.approx.f32 %0, %1;" : "=f"(r) : "f"(x)); return r;
}

#define LDSM_X4(r, addr) \
    asm volatile("ldmatrix.sync.aligned.m8n8.x4.shared.b16 {%0,%1,%2,%3}, [%4];" \
        : "=r"((r)[0]), "=r"((r)[1]), "=r"((r)[2]), "=r"((r)[3]) : "r"(addr))

__device__ __forceinline__ void mma_s8(int* c, const uint32_t* a, const uint32_t* b) {
    asm volatile(
        "mma.sync.aligned.m16n8k32.row.col.s32.s8.s8.s32 "
        "{%0,%1,%2,%3}, {%4,%5,%6,%7}, {%8,%9}, {%0,%1,%2,%3};"
        : "+r"(c[0]), "+r"(c[1]), "+r"(c[2]), "+r"(c[3])
        : "r"(a[0]), "r"(a[1]), "r"(a[2]), "r"(a[3]), "r"(b[0]), "r"(b[1]));
}

#define CP_COMMIT() asm volatile("cp.async.commit_group;" ::: "memory")
#define CP_WAIT0()  asm volatile("cp.async.wait_group 0;" ::: "memory")

// ---------------- zero per-call counters ----------------
__global__ void k_zero() {
    int t = threadIdx.x;
    if (t < CF) g_cnt_f[t] = 0;
    if (t < CR) g_cnt_r[t] = 0;
}

// ---------------- fused label histogram ----------------
__global__ void k_hist2(const int* __restrict__ tlab, const int* __restrict__ nlab) {
    __shared__ int sh[CR];
    bool fti = blockIdx.x < 256;
    const int* lab = fti ? tlab : nlab;
    int n   = fti ? NB : NR;
    int C   = fti ? CF : CR;
    int* cnt = fti ? g_cnt_f : g_cnt_r;
    int b   = fti ? blockIdx.x : blockIdx.x - 256;
    for (int i = threadIdx.x; i < C; i += blockDim.x) sh[i] = 0;
    __syncthreads();
    for (int i = b * blockDim.x + threadIdx.x; i < n; i += 256 * blockDim.x) {
        int l = lab[i];
        if (l >= 0) atomicAdd(&sh[l], 1);
    }
    __syncthreads();
    for (int i = threadIdx.x; i < C; i += blockDim.x)
        if (sh[i]) atomicAdd(&cnt[i], sh[i]);
}

// ---------------- exclusive scan ----------------
__global__ void k_scan() {
    __shared__ int sh[CR];
    int t = threadIdx.x;
    if (t < CF) sh[t] = g_cnt_f[t];
    __syncthreads();
    for (int o = 1; o < CF; o <<= 1) {
        int v = (t < CF && t >= o) ? sh[t - o] : 0;
        __syncthreads();
        if (t < CF) sh[t] += v;
        __syncthreads();
    }
    if (t < CF) { int e = sh[t] - g_cnt_f[t]; g_off_f[t] = e; g_cur_f[t] = e; }
    __syncthreads();
    if (t < CR) sh[t] = g_cnt_r[t];
    __syncthreads();
    for (int o = 1; o < CR; o <<= 1) {
        int v = (t < CR && t >= o) ? sh[t - o] : 0;
        __syncthreads();
        if (t < CR) sh[t] += v;
        __syncthreads();
    }
    if (t < CR) { int e = sh[t] - g_cnt_r[t]; g_off_r[t] = e; g_cur_r[t] = e; }
}

// ---------------- fused scatter ----------------
__global__ void k_scatter2(const int* __restrict__ tlab, const int* __restrict__ nlab) {
    int i = blockIdx.x * blockDim.x + threadIdx.x;
    if (i < NB) {
        int l = tlab[i];
        if (l >= 0) g_srt_f[atomicAdd(&g_cur_f[l], 1)] = i;
    } else {
        int j = i - NB;
        int l = nlab[j];
        if (l >= 0) g_srt_r[atomicAdd(&g_cur_r[l], 1)] = j;
    }
}

// ---------------- fused classsum + X int8 quantization ----------------
// Every labeled row passes through here exactly once; while the fp32 row is
// in registers we also emit the int8 row + fused loss scale.
// Lane holds floats [lane*4, lane*4+4) and [128+lane*4, 128+lane*4+4):
// packed words go to orow[lane] and orow[32+lane].
__global__ __launch_bounds__(256) void k_classsum2(
    const float* __restrict__ Xf, const float* __restrict__ Xr)
{
    __shared__ float sh[8][256];
    bool fti = blockIdx.x < CF;
    int c = fti ? blockIdx.x : blockIdx.x - CF;
    const float* x   = fti ? Xf : Xr;
    const int*   srt = fti ? g_srt_f : g_srt_r;
    int s0 = fti ? g_off_f[c] : g_off_r[c];
    int n  = fti ? g_cnt_f[c] : g_cnt_r[c];
    float* sums = (fti ? g_sum_f : g_sum_r) + c * D;
    int8_t* xq  = fti ? g_xq_f : g_xq_r;
    float*  xs  = fti ? g_xs_f : g_xs_r;

    int tid = threadIdx.x, w = tid >> 5, lane = tid & 31;
    float a0 = 0.f, a1 = 0.f, a2 = 0.f, a3 = 0.f;
    float b0 = 0.f, b1 = 0.f, b2 = 0.f, b3 = 0.f;
    for (int r = w; r < n; r += 8) {
        int idx = srt[s0 + r];
        const float4* row = (const float4*)(x + (size_t)idx * D);
        float4 fa = row[lane];
        float4 fb = row[32 + lane];
        float ss = fa.x*fa.x + fa.y*fa.y + fa.z*fa.z + fa.w*fa.w
                 + fb.x*fb.x + fb.y*fb.y + fb.z*fb.z + fb.w*fb.w;
        float mx = fmaxf(fmaxf(fmaxf(fabsf(fa.x), fabsf(fa.y)), fmaxf(fabsf(fa.z), fabsf(fa.w))),
                         fmaxf(fmaxf(fabsf(fb.x), fabsf(fb.y)), fmaxf(fabsf(fb.z), fabsf(fb.w))));
        #pragma unroll
        for (int o = 16; o; o >>= 1) {
            ss += __shfl_xor_sync(0xffffffffu, ss, o);
            mx  = fmaxf(mx, __shfl_xor_sync(0xffffffffu, mx, o));
        }
        mx = fmaxf(mx, 1e-30f);
        float inv = 1.0f / fmaxf(sqrtf(ss), EPSN);
        // int8 quantized row for the loss GEMM
        float qs = 127.f / mx;
        int q0 = __float2int_rn(fa.x * qs), q1 = __float2int_rn(fa.y * qs);
        int q2 = __float2int_rn(fa.z * qs), q3 = __float2int_rn(fa.w * qs);
        int q4 = __float2int_rn(fb.x * qs), q5 = __float2int_rn(fb.y * qs);
        int q6 = __float2int_rn(fb.z * qs), q7 = __float2int_rn(fb.w * qs);
        uint32_t p0 = (q0 & 0xFF) | ((q1 & 0xFF) << 8) | ((q2 & 0xFF) << 16) | ((q3 & 0xFF) << 24);
        uint32_t p1 = (q4 & 0xFF) | ((q5 & 0xFF) << 8) | ((q6 & 0xFF) << 16) | ((q7 & 0xFF) << 24);
        uint32_t* orow = (uint32_t*)(xq + (size_t)idx * D);
        orow[lane]      = p0;   // bytes [lane*4, lane*4+4)
        orow[32 + lane] = p1;   // bytes [128+lane*4, ...)
        if (lane == 0) xs[idx] = SC2 * inv * mx * (1.f / 127.f);
        // normalized fp32 class-sum accumulation (exact, as before)
        a0 += fa.x * inv; a1 += fa.y * inv; a2 += fa.z * inv; a3 += fa.w * inv;
        b0 += fb.x * inv; b1 += fb.y * inv; b2 += fb.z * inv; b3 += fb.w * inv;
    }
    sh[w][lane * 4 + 0] = a0; sh[w][lane * 4 + 1] = a1;
    sh[w][lane * 4 + 2] = a2; sh[w][lane * 4 + 3] = a3;
    sh[w][128 + lane * 4 + 0] = b0; sh[w][128 + lane * 4 + 1] = b1;
    sh[w][128 + lane * 4 + 2] = b2; sh[w][128 + lane * 4 + 3] = b3;
    __syncthreads();
    float s = 0.f;
    #pragma unroll
    for (int ww = 0; ww < 8; ww++) s += sh[ww][tid];
    sums[tid] = s;
}

// ---------------- fused prototype EMA update -> int8 + per-class scale ----------------
__global__ __launch_bounds__(256) void k_proto2(
    const float* __restrict__ pf, const float* __restrict__ pr)
{
    __shared__ float sh[256];
    bool fti = blockIdx.x < CF;
    int c = fti ? blockIdx.x : blockIdx.x - CF;
    int n = fti ? g_cnt_f[c] : g_cnt_r[c];
    const float* sums = (fti ? g_sum_f : g_sum_r) + c * D;
    const float* pin  = (fti ? pf : pr) + c * D;
    int8_t* pout = (fti ? g_pbq_f : g_pbq_r) + c * D;
    float*  psc  = fti ? g_pbs_f : g_pbs_r;

    int t = threadIdx.x;
    float mv = sums[t] / fmaxf((float)n, 1.f);
    sh[t] = mv * mv;
    __syncthreads();
    #pragma unroll
    for (int o = 128; o; o >>= 1) { if (t < o) sh[t] += sh[t + o]; __syncthreads(); }
    float nm = fmaxf(sqrtf(sh[0]), EPSN);
    __syncthreads();
    mv = mv / nm;
    float p = pin[t];
    float q = 0.5f * p + 0.5f * mv;
    sh[t] = q * q;
    __syncthreads();
    #pragma unroll
    for (int o = 128; o; o >>= 1) { if (t < o) sh[t] += sh[t + o]; __syncthreads(); }
    float nq = fmaxf(sqrtf(sh[0]), EPSN);
    float val = (n > 0) ? q / nq : p;
    __syncthreads();
    sh[t] = fabsf(val);
    __syncthreads();
    #pragma unroll
    for (int o = 128; o; o >>= 1) { if (t < o) sh[t] = fmaxf(sh[t], sh[t + o]); __syncthreads(); }
    float m = fmaxf(sh[0], 1e-30f);
    int qv = __float2int_rn(val * (127.f / m));
    qv = max(-127, min(127, qv));
    pout[t] = (int8_t)qv;
    if (t == 0) psc[c] = m * (1.f / 127.f);
}

// ---------------- int8 mma.sync fused GEMM + softmax CE ----------------
// A and B both int8, loaded via cp.async (A precomputed in classsum).
// smem: 0 lab | 512 scale | 1024 rs | 2048 tg | 3072 red | 3200 scb[512]
//       5376 A(34816) | 40192 B0(34816) | 75008 B1(34816) -> 109824 (2 CTA/SM)
#define A_OFF   5376
#define B0_OFF  40192
#define BBUF    34816
#define SMEM_LOSS 109824
#define NBLK_R (NR/128)

__device__ __forceinline__ void prefetch_T(uint32_t sbu, uint32_t dstOff,
                                           const int8_t* __restrict__ P,
                                           int r0, int tid) {
    #pragma unroll
    for (int i = 0; i < 8; i++) {
        int ch = tid + i * 256;           // 2048 chunks of 16 bytes
        int r  = ch >> 4;                 // row 0..127
        int c16 = (ch & 15) * 16;         // k byte 0..240
        uint32_t dst = sbu + dstOff + (uint32_t)(r * 272 + c16);
        const void* src = P + (size_t)(r0 + r) * D + c16;
        asm volatile("cp.async.cg.shared.global [%0], [%1], 16;" :: "r"(dst), "l"(src));
    }
}

__global__ __launch_bounds__(256, 2)
void k_loss_tc(const int* __restrict__ tlab, const int* __restrict__ nlab)
{
    extern __shared__ char smem[];
    int*   lab_sm   = (int*)(smem + 0);
    float* scale_sm = (float*)(smem + 512);
    float* rs_sm    = (float*)(smem + 1024);
    float* tg_sm    = (float*)(smem + 2048);
    float* red_s    = (float*)(smem + 3072);
    float* red_c    = (float*)(smem + 3104);
    float* scb_sm   = (float*)(smem + 3200);

    // heavy rcl blocks first, light fti blocks backfill the tail
    const bool fti = blockIdx.x >= NBLK_R;
    const int  bid = fti ? blockIdx.x - NBLK_R : blockIdx.x;
    const int8_t* Xq = fti ? g_xq_f : g_xq_r;
    const float*  Xs = fti ? g_xs_f : g_xs_r;
    const int8_t* Pq = fti ? g_pbq_f : g_pbq_r;
    const float*  Ps = fti ? g_pbs_f : g_pbs_r;
    const int* lab = fti ? tlab : nlab;
    float* lsum = fti ? g_ls_f : g_ls_r;
    float* lcnt = fti ? g_lc_f : g_lc_r;
    const int NCH = fti ? (CF / 128) : (CR / 128);

    const int tid  = threadIdx.x;
    const int wid  = tid >> 5;
    const int lane = tid & 31;
    const int wr   = wid & 3;
    const int wc   = wid >> 2;
    const int row0 = bid * 128;
    const uint32_t sbu = smem_u32(smem);

    // A tile + B chunk 0 via cp.async, scales/labels via regular loads
    prefetch_T(sbu, A_OFF, Xq, row0, tid);
    prefetch_T(sbu, B0_OFF, Pq, 0, tid);
    CP_COMMIT();
    if (tid < 128) {
        lab_sm[tid]   = lab[row0 + tid];
        scale_sm[tid] = Xs[row0 + tid];
    }
    for (int i = tid; i < NCH * 128; i += 256) scb_sm[i] = Ps[i];
    CP_WAIT0();
    __syncthreads();

    int lb4[4]; float sc4[4];
    #pragma unroll
    for (int mt = 0; mt < 2; mt++)
        #pragma unroll
        for (int h = 0; h < 2; h++) {
            int r = wr * 32 + mt * 16 + (lane >> 2) + h * 8;
            lb4[mt * 2 + h] = lab_sm[r];
            sc4[mt * 2 + h] = scale_sm[r];
        }

    const uint32_t aBase = sbu + A_OFF
        + (uint32_t)(wr * 32 + (lane & 15)) * 272 + (uint32_t)(lane >> 4) * 16;
    const uint32_t bB0 = sbu + B0_OFF
        + (uint32_t)(wc * 64 + (lane & 7) + ((lane >> 4) & 1) * 8) * 272
        + (uint32_t)((lane >> 3) & 1) * 16;

    float ssum[4] = {0.f, 0.f, 0.f, 0.f};
    float tgt[4]  = {0.f, 0.f, 0.f, 0.f};

    for (int c = 0; c < NCH; c++) {
        if (c) { CP_WAIT0(); __syncthreads(); }
        if (c + 1 < NCH) {
            prefetch_T(sbu, B0_OFF + (uint32_t)((c + 1) & 1) * BBUF, Pq, (c + 1) * 128, tid);
            CP_COMMIT();
        }
        const uint32_t bBase = bB0 + (uint32_t)(c & 1) * BBUF;

        int acc[2][8][4];
        #pragma unroll
        for (int mt = 0; mt < 2; mt++)
            #pragma unroll
            for (int nt = 0; nt < 8; nt++)
                #pragma unroll
                for (int e = 0; e < 4; e++) acc[mt][nt][e] = 0;

        #pragma unroll
        for (int k = 0; k < 8; k++) {
            uint32_t aoff = (uint32_t)k * 32;
            uint32_t ah0[4], ah1[4];
            LDSM_X4(ah0, aBase + aoff);
            LDSM_X4(ah1, aBase + 4352 + aoff);
            #pragma unroll
            for (int ntp = 0; ntp < 4; ntp++) {
                uint32_t bh[4];
                LDSM_X4(bh, bBase + (uint32_t)ntp * 4352 + aoff);
                mma_s8(acc[0][ntp*2],   ah0, bh);
                mma_s8(acc[1][ntp*2],   ah1, bh);
                mma_s8(acc[0][ntp*2+1], ah0, bh + 2);
                mma_s8(acc[1][ntp*2+1], ah1, bh + 2);
            }
        }

        int c0 = c * 128;
        #pragma unroll
        for (int nt = 0; nt < 8; nt++) {
            int colb = c0 + wc * 64 + nt * 8 + (lane & 3) * 2;
            float sb0 = scb_sm[colb];
            float sb1 = scb_sm[colb + 1];
            #pragma unroll
            for (int mt = 0; mt < 2; mt++) {
                float l0 = __int2float_rn(acc[mt][nt][0]) * sc4[mt*2]   * sb0;
                float l1 = __int2float_rn(acc[mt][nt][1]) * sc4[mt*2]   * sb1;
                float l2 = __int2float_rn(acc[mt][nt][2]) * sc4[mt*2+1] * sb0;
                float l3 = __int2float_rn(acc[mt][nt][3]) * sc4[mt*2+1] * sb1;
                ssum[mt*2]   += ex2f_fast(l0) + ex2f_fast(l1);
                ssum[mt*2+1] += ex2f_fast(l2) + ex2f_fast(l3);
                if (lb4[mt*2]   == colb)     tgt[mt*2]   = l0;
                if (lb4[mt*2]   == colb + 1) tgt[mt*2]   = l1;
                if (lb4[mt*2+1] == colb)     tgt[mt*2+1] = l2;
                if (lb4[mt*2+1] == colb + 1) tgt[mt*2+1] = l3;
            }
        }
    }

    #pragma unroll
    for (int i = 0; i < 4; i++) {
        ssum[i] += __shfl_xor_sync(0xffffffffu, ssum[i], 1);
        ssum[i] += __shfl_xor_sync(0xffffffffu, ssum[i], 2);
        tgt[i]  += __shfl_xor_sync(0xffffffffu, tgt[i], 1);
        tgt[i]  += __shfl_xor_sync(0xffffffffu, tgt[i], 2);
    }
    if ((lane & 3) == 0) {
        #pragma unroll
        for (int i = 0; i < 4; i++) {
            int r = wr * 32 + (i >> 1) * 16 + (lane >> 2) + (i & 1) * 8;
            rs_sm[r * 2 + wc] = ssum[i];
            tg_sm[r * 2 + wc] = tgt[i];
        }
    }
    __syncthreads();

    float v = 0.f, cn = 0.f;
    if (tid < 128) {
        int lb = lab_sm[tid];
        if (lb >= 0) {
            float S  = rs_sm[tid * 2] + rs_sm[tid * 2 + 1];
            float T2 = tg_sm[tid * 2] + tg_sm[tid * 2 + 1];
            v  = LN2 * (lg2f_fast(S) - T2);
            cn = 1.f;
        }
    }
    #pragma unroll
    for (int o = 16; o; o >>= 1) {
        v  += __shfl_xor_sync(0xffffffffu, v, o);
        cn += __shfl_xor_sync(0xffffffffu, cn, o);
    }
    if (lane == 0) { red_s[wid] = v; red_c[wid] = cn; }
    __syncthreads();
    if (tid == 0) {
        lsum[bid] = red_s[0] + red_s[1] + red_s[2] + red_s[3];
        lcnt[bid] = red_c[0] + red_c[1] + red_c[2] + red_c[3];
    }
}

// ---------------- final reduction of per-block partials ----------------
__global__ void k_final(float* __restrict__ out) {
    __shared__ float sh[1024];
    int t = threadIdx.x;
    float v;

    v = (t < NB / 128) ? g_ls_f[t] : 0.f;
    sh[t] = v; __syncthreads();
    #pragma unroll
    for (int o = 512; o; o >>= 1) { if (t < o) sh[t] += sh[t + o]; __syncthreads(); }
    float sf = sh[0]; __syncthreads();

    v = (t < NB / 128) ? g_lc_f[t] : 0.f;
    sh[t] = v; __syncthreads();
    #pragma unroll
    for (int o = 512; o; o >>= 1) { if (t < o) sh[t] += sh[t + o]; __syncthreads(); }
    float cf = sh[0]; __syncthreads();

    v = g_ls_r[t];
    sh[t] = v; __syncthreads();
    #pragma unroll
    for (int o = 512; o; o >>= 1) { if (t < o) sh[t] += sh[t + o]; __syncthreads(); }
    float sr = sh[0]; __syncthreads();

    v = g_lc_r[t];
    sh[t] = v; __syncthreads();
    #pragma unroll
    for (int o = 512; o; o >>= 1) { if (t < o) sh[t] += sh[t + o]; __syncthreads(); }
    float cr = sh[0];

    if (t == 0) {
        out[0] = sf / fmaxf(cf, 1.f);
        out[1] = sr / fmaxf(cr, 1.f);
    }
}

// ---------------- host launcher (graph-capturable, allocation-free) ----------------
extern "C" void kernel_launch(void* const* d_in, const int* in_sizes, int n_in,
                              void* d_out, int out_size) {
    (void)in_sizes; (void)n_in; (void)out_size;
    const float* f_fti = (const float*)d_in[0];
    const float* e_rcl = (const float*)d_in[1];
    const int*   tlab  = (const int*)d_in[2];
    const int*   nlab  = (const int*)d_in[3];
    const float* pf    = (const float*)d_in[4];
    const float* pr    = (const float*)d_in[5];
    float* out = (float*)d_out;

    cudaFuncSetAttribute(k_loss_tc, cudaFuncAttributeMaxDynamicSharedMemorySize, SMEM_LOSS);

    k_zero<<<1, 512>>>();
    k_hist2<<<512, 256>>>(tlab, nlab);
    k_scan<<<1, 512>>>();
    k_scatter2<<<(NB + NR) / 256, 256>>>(tlab, nlab);
    k_classsum2<<<CF + CR, 256>>>(f_fti, e_rcl);
    k_proto2<<<CF + CR, 256>>>(pf, pr);
    k_loss_tc<<<NR / 128 + NB / 128, 256, SMEM_LOSS>>>(tlab, nlab);
    k_final<<<1, 1024>>>(out);
}

// round 13
// speedup vs baseline: 5.8350x; 1.0072x over previous
#include <cuda_runtime.h>
#include <cuda_bf16.h>
#include <math.h>
#include <stdint.h>

#define D   256
#define NB  65536
#define NR  131072
#define CF  128
#define CR  512
#define HB  64     // hist blocks per branch
#define EPSN  1e-12f
// (1/T) * log2(e)
#define SC2 4.8089834696296117f
#define LN2 0.6931471805599453f

// ---------------- scratch (static device globals; no runtime alloc) ----------------
__device__ int   g_ph_f[HB*CF];    // per-block partial histograms (fully overwritten)
__device__ int   g_ph_r[HB*CR];
__device__ int   g_cnt_f[CF];
__device__ int   g_cnt_r[CR];
__device__ int   g_off_f[CF];
__device__ int   g_off_r[CR];
__device__ int   g_cur_f[CF];
__device__ int   g_cur_r[CR];
__device__ int   g_srt_f[NB];
__device__ int   g_srt_r[NR];
__device__ float g_sum_f[CF*D];
__device__ float g_sum_r[CR*D];
__device__ int8_t g_xq_f[NB*D];    // quantized features (written by classsum)
__device__ int8_t g_xq_r[NR*D];
__device__ float  g_xs_f[NB];      // fused per-row scale SC2*inv*mx/127
__device__ float  g_xs_r[NR];
__device__ int8_t g_pbq_f[CF*D];   // updated prototypes, int8
__device__ int8_t g_pbq_r[CR*D];
__device__ float  g_pbs_f[CF];     // per-class dequant scale (max/127)
__device__ float  g_pbs_r[CR];
__device__ float g_ls_f[NB/128];
__device__ float g_lc_f[NB/128];
__device__ float g_ls_r[NR/128];
__device__ float g_lc_r[NR/128];

__device__ __forceinline__ uint32_t smem_u32(const void* p) {
    uint32_t a;
    asm("{ .reg .u64 t; cvta.to.shared.u64 t, %1; cvt.u32.u64 %0, t; }" : "=r"(a) : "l"(p));
    return a;
}
__device__ __forceinline__ float ex2f_fast(float x) {
    float r; asm("ex2.approx.f32 %0, %1;" : "=f"(r) : "f"(x)); return r;
}
__device__ __forceinline__ float lg2f_fast(float x) {
    float r; asm("lg2.approx.f32 %0, %1;" : "=f"(r) : "f"(x)); return r;
}

#define LDSM_X4(r, addr) \
    asm volatile("ldmatrix.sync.aligned.m8n8.x4.shared.b16 {%0,%1,%2,%3}, [%4];" \
        : "=r"((r)[0]), "=r"((r)[1]), "=r"((r)[2]), "=r"((r)[3]) : "r"(addr))

__device__ __forceinline__ void mma_s8(int* c, const uint32_t* a, const uint32_t* b) {
    asm volatile(
        "mma.sync.aligned.m16n8k32.row.col.s32.s8.s8.s32 "
        "{%0,%1,%2,%3}, {%4,%5,%6,%7}, {%8,%9}, {%0,%1,%2,%3};"
        : "+r"(c[0]), "+r"(c[1]), "+r"(c[2]), "+r"(c[3])
        : "r"(a[0]), "r"(a[1]), "r"(a[2]), "r"(a[3]), "r"(b[0]), "r"(b[1]));
}

#define CP_COMMIT() asm volatile("cp.async.commit_group;" ::: "memory")
#define CP_WAIT0()  asm volatile("cp.async.wait_group 0;" ::: "memory")

// ---------------- partial histograms: no global atomics, nothing to zero ----------------
__global__ __launch_bounds__(256) void k_histp(
    const int* __restrict__ tlab, const int* __restrict__ nlab)
{
    __shared__ int sh[CR];
    bool fti = blockIdx.x < HB;
    const int* lab = fti ? tlab : nlab;
    int n = fti ? NB : NR;
    int C = fti ? CF : CR;
    int b = fti ? blockIdx.x : blockIdx.x - HB;
    int tid = threadIdx.x;
    for (int i = tid; i < C; i += 256) sh[i] = 0;
    __syncthreads();
    for (int i = b * 256 + tid; i < n; i += HB * 256) {
        int l = lab[i];
        if (l >= 0) atomicAdd(&sh[l], 1);
    }
    __syncthreads();
    int* dst = fti ? (g_ph_f + b * CF) : (g_ph_r + b * CR);
    for (int i = tid; i < C; i += 256) dst[i] = sh[i];
}

// ---------------- sum partials + exclusive scan (1 block) ----------------
__global__ void k_scan() {
    __shared__ int sh[CR];
    int t = threadIdx.x;
    int myc_f = 0, myc_r = 0;
    if (t < CF) {
        int s = 0;
        #pragma unroll 8
        for (int j = 0; j < HB; j++) s += g_ph_f[j * CF + t];
        myc_f = s; g_cnt_f[t] = s; sh[t] = s;
    }
    __syncthreads();
    for (int o = 1; o < CF; o <<= 1) {
        int v = (t < CF && t >= o) ? sh[t - o] : 0;
        __syncthreads();
        if (t < CF) sh[t] += v;
        __syncthreads();
    }
    if (t < CF) { int e = sh[t] - myc_f; g_off_f[t] = e; g_cur_f[t] = e; }
    __syncthreads();
    if (t < CR) {
        int s = 0;
        #pragma unroll 8
        for (int j = 0; j < HB; j++) s += g_ph_r[j * CR + t];
        myc_r = s; g_cnt_r[t] = s; sh[t] = s;
    }
    __syncthreads();
    for (int o = 1; o < CR; o <<= 1) {
        int v = (t < CR && t >= o) ? sh[t - o] : 0;
        __syncthreads();
        if (t < CR) sh[t] += v;
        __syncthreads();
    }
    if (t < CR) { int e = sh[t] - myc_r; g_off_r[t] = e; g_cur_r[t] = e; }
}

// ---------------- warp-aggregated scatter ----------------
// NB is a multiple of blockDim, so no warp straddles the branch boundary.
__global__ void k_scatter2(const int* __restrict__ tlab, const int* __restrict__ nlab) {
    int i = blockIdx.x * blockDim.x + threadIdx.x;
    int lane = threadIdx.x & 31;
    int idx, l;
    int* cur;
    int* srt;
    if (i < NB) { idx = i;      l = tlab[idx]; cur = g_cur_f; srt = g_srt_f; }
    else        { idx = i - NB; l = nlab[idx]; cur = g_cur_r; srt = g_srt_r; }
    if (l >= 0) {
        unsigned am   = __activemask();
        unsigned mask = __match_any_sync(am, l);
        int leader = __ffs(mask) - 1;
        int rank   = __popc(mask & ((1u << lane) - 1));
        int base = 0;
        if (lane == leader) base = atomicAdd(&cur[l], __popc(mask));
        base = __shfl_sync(mask, base, leader);
        srt[base + rank] = idx;
    }
}

// ---------------- fused classsum + X int8 quantization ----------------
// Lane holds floats [lane*4, +4) and [128+lane*4, +4): packed words go to
// orow[lane] and orow[32+lane].
__global__ __launch_bounds__(256) void k_classsum2(
    const float* __restrict__ Xf, const float* __restrict__ Xr)
{
    __shared__ float sh[8][256];
    bool fti = blockIdx.x < CF;
    int c = fti ? blockIdx.x : blockIdx.x - CF;
    const float* x   = fti ? Xf : Xr;
    const int*   srt = fti ? g_srt_f : g_srt_r;
    int s0 = fti ? g_off_f[c] : g_off_r[c];
    int n  = fti ? g_cnt_f[c] : g_cnt_r[c];
    float* sums = (fti ? g_sum_f : g_sum_r) + c * D;
    int8_t* xq  = fti ? g_xq_f : g_xq_r;
    float*  xs  = fti ? g_xs_f : g_xs_r;

    int tid = threadIdx.x, w = tid >> 5, lane = tid & 31;
    float a0 = 0.f, a1 = 0.f, a2 = 0.f, a3 = 0.f;
    float b0 = 0.f, b1 = 0.f, b2 = 0.f, b3 = 0.f;
    for (int r = w; r < n; r += 8) {
        int idx = srt[s0 + r];
        const float4* row = (const float4*)(x + (size_t)idx * D);
        float4 fa = row[lane];
        float4 fb = row[32 + lane];
        float ss = fa.x*fa.x + fa.y*fa.y + fa.z*fa.z + fa.w*fa.w
                 + fb.x*fb.x + fb.y*fb.y + fb.z*fb.z + fb.w*fb.w;
        float mx = fmaxf(fmaxf(fmaxf(fabsf(fa.x), fabsf(fa.y)), fmaxf(fabsf(fa.z), fabsf(fa.w))),
                         fmaxf(fmaxf(fabsf(fb.x), fabsf(fb.y)), fmaxf(fabsf(fb.z), fabsf(fb.w))));
        #pragma unroll
        for (int o = 16; o; o >>= 1) {
            ss += __shfl_xor_sync(0xffffffffu, ss, o);
            mx  = fmaxf(mx, __shfl_xor_sync(0xffffffffu, mx, o));
        }
        mx = fmaxf(mx, 1e-30f);
        float inv = 1.0f / fmaxf(sqrtf(ss), EPSN);
        float qs = 127.f / mx;
        int q0 = __float2int_rn(fa.x * qs), q1 = __float2int_rn(fa.y * qs);
        int q2 = __float2int_rn(fa.z * qs), q3 = __float2int_rn(fa.w * qs);
        int q4 = __float2int_rn(fb.x * qs), q5 = __float2int_rn(fb.y * qs);
        int q6 = __float2int_rn(fb.z * qs), q7 = __float2int_rn(fb.w * qs);
        uint32_t p0 = (q0 & 0xFF) | ((q1 & 0xFF) << 8) | ((q2 & 0xFF) << 16) | ((q3 & 0xFF) << 24);
        uint32_t p1 = (q4 & 0xFF) | ((q5 & 0xFF) << 8) | ((q6 & 0xFF) << 16) | ((q7 & 0xFF) << 24);
        uint32_t* orow = (uint32_t*)(xq + (size_t)idx * D);
        orow[lane]      = p0;   // bytes [lane*4, lane*4+4)
        orow[32 + lane] = p1;   // bytes [128+lane*4, ...)
        if (lane == 0) xs[idx] = SC2 * inv * mx * (1.f / 127.f);
        a0 += fa.x * inv; a1 += fa.y * inv; a2 += fa.z * inv; a3 += fa.w * inv;
        b0 += fb.x * inv; b1 += fb.y * inv; b2 += fb.z * inv; b3 += fb.w * inv;
    }
    sh[w][lane * 4 + 0] = a0; sh[w][lane * 4 + 1] = a1;
    sh[w][lane * 4 + 2] = a2; sh[w][lane * 4 + 3] = a3;
    sh[w][128 + lane * 4 + 0] = b0; sh[w][128 + lane * 4 + 1] = b1;
    sh[w][128 + lane * 4 + 2] = b2; sh[w][128 + lane * 4 + 3] = b3;
    __syncthreads();
    float s = 0.f;
    #pragma unroll
    for (int ww = 0; ww < 8; ww++) s += sh[ww][tid];
    sums[tid] = s;
}

// ---------------- fused prototype EMA update -> int8 + per-class scale ----------------
__global__ __launch_bounds__(256) void k_proto2(
    const float* __restrict__ pf, const float* __restrict__ pr)
{
    __shared__ float sh[256];
    bool fti = blockIdx.x < CF;
    int c = fti ? blockIdx.x : blockIdx.x - CF;
    int n = fti ? g_cnt_f[c] : g_cnt_r[c];
    const float* sums = (fti ? g_sum_f : g_sum_r) + c * D;
    const float* pin  = (fti ? pf : pr) + c * D;
    int8_t* pout = (fti ? g_pbq_f : g_pbq_r) + c * D;
    float*  psc  = fti ? g_pbs_f : g_pbs_r;

    int t = threadIdx.x;
    float mv = sums[t] / fmaxf((float)n, 1.f);
    sh[t] = mv * mv;
    __syncthreads();
    #pragma unroll
    for (int o = 128; o; o >>= 1) { if (t < o) sh[t] += sh[t + o]; __syncthreads(); }
    float nm = fmaxf(sqrtf(sh[0]), EPSN);
    __syncthreads();
    mv = mv / nm;
    float p = pin[t];
    float q = 0.5f * p + 0.5f * mv;
    sh[t] = q * q;
    __syncthreads();
    #pragma unroll
    for (int o = 128; o; o >>= 1) { if (t < o) sh[t] += sh[t + o]; __syncthreads(); }
    float nq = fmaxf(sqrtf(sh[0]), EPSN);
    float val = (n > 0) ? q / nq : p;
    __syncthreads();
    sh[t] = fabsf(val);
    __syncthreads();
    #pragma unroll
    for (int o = 128; o; o >>= 1) { if (t < o) sh[t] = fmaxf(sh[t], sh[t + o]); __syncthreads(); }
    float m = fmaxf(sh[0], 1e-30f);
    int qv = __float2int_rn(val * (127.f / m));
    qv = max(-127, min(127, qv));
    pout[t] = (int8_t)qv;
    if (t == 0) psc[c] = m * (1.f / 127.f);
}

// ---------------- int8 mma.sync fused GEMM + softmax CE ----------------
// smem: 0 lab | 512 scale | 1024 rs | 2048 tg | 3072 red | 3200 scb[512]
//       5376 A(34816) | 40192 B0(34816) | 75008 B1(34816) -> 109824 (2 CTA/SM)
#define A_OFF   5376
#define B0_OFF  40192
#define BBUF    34816
#define SMEM_LOSS 109824
#define NBLK_R (NR/128)

__device__ __forceinline__ void prefetch_T(uint32_t sbu, uint32_t dstOff,
                                           const int8_t* __restrict__ P,
                                           int r0, int tid) {
    #pragma unroll
    for (int i = 0; i < 8; i++) {
        int ch = tid + i * 256;
        int r  = ch >> 4;
        int c16 = (ch & 15) * 16;
        uint32_t dst = sbu + dstOff + (uint32_t)(r * 272 + c16);
        const void* src = P + (size_t)(r0 + r) * D + c16;
        asm volatile("cp.async.cg.shared.global [%0], [%1], 16;" :: "r"(dst), "l"(src));
    }
}

__global__ __launch_bounds__(256, 2)
void k_loss_tc(const int* __restrict__ tlab, const int* __restrict__ nlab)
{
    extern __shared__ char smem[];
    int*   lab_sm   = (int*)(smem + 0);
    float* scale_sm = (float*)(smem + 512);
    float* rs_sm    = (float*)(smem + 1024);
    float* tg_sm    = (float*)(smem + 2048);
    float* red_s    = (float*)(smem + 3072);
    float* red_c    = (float*)(smem + 3104);
    float* scb_sm   = (float*)(smem + 3200);

    // heavy rcl blocks first, light fti blocks backfill the tail
    const bool fti = blockIdx.x >= NBLK_R;
    const int  bid = fti ? blockIdx.x - NBLK_R : blockIdx.x;
    const int8_t* Xq = fti ? g_xq_f : g_xq_r;
    const float*  Xs = fti ? g_xs_f : g_xs_r;
    const int8_t* Pq = fti ? g_pbq_f : g_pbq_r;
    const float*  Ps = fti ? g_pbs_f : g_pbs_r;
    const int* lab = fti ? tlab : nlab;
    float* lsum = fti ? g_ls_f : g_ls_r;
    float* lcnt = fti ? g_lc_f : g_lc_r;
    const int NCH = fti ? (CF / 128) : (CR / 128);

    const int tid  = threadIdx.x;
    const int wid  = tid >> 5;
    const int lane = tid & 31;
    const int wr   = wid & 3;
    const int wc   = wid >> 2;
    const int row0 = bid * 128;
    const uint32_t sbu = smem_u32(smem);

    prefetch_T(sbu, A_OFF, Xq, row0, tid);
    prefetch_T(sbu, B0_OFF, Pq, 0, tid);
    CP_COMMIT();
    if (tid < 128) {
        lab_sm[tid]   = lab[row0 + tid];
        scale_sm[tid] = Xs[row0 + tid];
    }
    for (int i = tid; i < NCH * 128; i += 256) scb_sm[i] = Ps[i];
    CP_WAIT0();
    __syncthreads();

    int lb4[4]; float sc4[4];
    #pragma unroll
    for (int mt = 0; mt < 2; mt++)
        #pragma unroll
        for (int h = 0; h < 2; h++) {
            int r = wr * 32 + mt * 16 + (lane >> 2) + h * 8;
            lb4[mt * 2 + h] = lab_sm[r];
            sc4[mt * 2 + h] = scale_sm[r];
        }

    const uint32_t aBase = sbu + A_OFF
        + (uint32_t)(wr * 32 + (lane & 15)) * 272 + (uint32_t)(lane >> 4) * 16;
    const uint32_t bB0 = sbu + B0_OFF
        + (uint32_t)(wc * 64 + (lane & 7) + ((lane >> 4) & 1) * 8) * 272
        + (uint32_t)((lane >> 3) & 1) * 16;

    float ssum[4] = {0.f, 0.f, 0.f, 0.f};
    float tgt[4]  = {0.f, 0.f, 0.f, 0.f};

    for (int c = 0; c < NCH; c++) {
        if (c) { CP_WAIT0(); __syncthreads(); }
        if (c + 1 < NCH) {
            prefetch_T(sbu, B0_OFF + (uint32_t)((c + 1) & 1) * BBUF, Pq, (c + 1) * 128, tid);
            CP_COMMIT();
        }
        const uint32_t bBase = bB0 + (uint32_t)(c & 1) * BBUF;

        int acc[2][8][4];
        #pragma unroll
        for (int mt = 0; mt < 2; mt++)
            #pragma unroll
            for (int nt = 0; nt < 8; nt++)
                #pragma unroll
                for (int e = 0; e < 4; e++) acc[mt][nt][e] = 0;

        #pragma unroll
        for (int k = 0; k < 8; k++) {
            uint32_t aoff = (uint32_t)k * 32;
            uint32_t ah0[4], ah1[4];
            LDSM_X4(ah0, aBase + aoff);
            LDSM_X4(ah1, aBase + 4352 + aoff);
            #pragma unroll
            for (int ntp = 0; ntp < 4; ntp++) {
                uint32_t bh[4];
                LDSM_X4(bh, bBase + (uint32_t)ntp * 4352 + aoff);
                mma_s8(acc[0][ntp*2],   ah0, bh);
                mma_s8(acc[1][ntp*2],   ah1, bh);
                mma_s8(acc[0][ntp*2+1], ah0, bh + 2);
                mma_s8(acc[1][ntp*2+1], ah1, bh + 2);
            }
        }

        int c0 = c * 128;
        #pragma unroll
        for (int nt = 0; nt < 8; nt++) {
            int colb = c0 + wc * 64 + nt * 8 + (lane & 3) * 2;
            float sb0 = scb_sm[colb];
            float sb1 = scb_sm[colb + 1];
            #pragma unroll
            for (int mt = 0; mt < 2; mt++) {
                float l0 = __int2float_rn(acc[mt][nt][0]) * sc4[mt*2]   * sb0;
                float l1 = __int2float_rn(acc[mt][nt][1]) * sc4[mt*2]   * sb1;
                float l2 = __int2float_rn(acc[mt][nt][2]) * sc4[mt*2+1] * sb0;
                float l3 = __int2float_rn(acc[mt][nt][3]) * sc4[mt*2+1] * sb1;
                ssum[mt*2]   += ex2f_fast(l0) + ex2f_fast(l1);
                ssum[mt*2+1] += ex2f_fast(l2) + ex2f_fast(l3);
                if (lb4[mt*2]   == colb)     tgt[mt*2]   = l0;
                if (lb4[mt*2]   == colb + 1) tgt[mt*2]   = l1;
                if (lb4[mt*2+1] == colb)     tgt[mt*2+1] = l2;
                if (lb4[mt*2+1] == colb + 1) tgt[mt*2+1] = l3;
            }
        }
    }

    #pragma unroll
    for (int i = 0; i < 4; i++) {
        ssum[i] += __shfl_xor_sync(0xffffffffu, ssum[i], 1);
        ssum[i] += __shfl_xor_sync(0xffffffffu, ssum[i], 2);
        tgt[i]  += __shfl_xor_sync(0xffffffffu, tgt[i], 1);
        tgt[i]  += __shfl_xor_sync(0xffffffffu, tgt[i], 2);
    }
    if ((lane & 3) == 0) {
        #pragma unroll
        for (int i = 0; i < 4; i++) {
            int r = wr * 32 + (i >> 1) * 16 + (lane >> 2) + (i & 1) * 8;
            rs_sm[r * 2 + wc] = ssum[i];
            tg_sm[r * 2 + wc] = tgt[i];
        }
    }
    __syncthreads();

    float v = 0.f, cn = 0.f;
    if (tid < 128) {
        int lb = lab_sm[tid];
        if (lb >= 0) {
            float S  = rs_sm[tid * 2] + rs_sm[tid * 2 + 1];
            float T2 = tg_sm[tid * 2] + tg_sm[tid * 2 + 1];
            v  = LN2 * (lg2f_fast(S) - T2);
            cn = 1.f;
        }
    }
    #pragma unroll
    for (int o = 16; o; o >>= 1) {
        v  += __shfl_xor_sync(0xffffffffu, v, o);
        cn += __shfl_xor_sync(0xffffffffu, cn, o);
    }
    if (lane == 0) { red_s[wid] = v; red_c[wid] = cn; }
    __syncthreads();
    if (tid == 0) {
        lsum[bid] = red_s[0] + red_s[1] + red_s[2] + red_s[3];
        lcnt[bid] = red_c[0] + red_c[1] + red_c[2] + red_c[3];
    }
}

// ---------------- final reduction of per-block partials ----------------
__global__ void k_final(float* __restrict__ out) {
    __shared__ float sh[1024];
    int t = threadIdx.x;
    float v;

    v = (t < NB / 128) ? g_ls_f[t] : 0.f;
    sh[t] = v; __syncthreads();
    #pragma unroll
    for (int o = 512; o; o >>= 1) { if (t < o) sh[t] += sh[t + o]; __syncthreads(); }
    float sf = sh[0]; __syncthreads();

    v = (t < NB / 128) ? g_lc_f[t] : 0.f;
    sh[t] = v; __syncthreads();
    #pragma unroll
    for (int o = 512; o; o >>= 1) { if (t < o) sh[t] += sh[t + o]; __syncthreads(); }
    float cf = sh[0]; __syncthreads();

    v = g_ls_r[t];
    sh[t] = v; __syncthreads();
    #pragma unroll
    for (int o = 512; o; o >>= 1) { if (t < o) sh[t] += sh[t + o]; __syncthreads(); }
    float sr = sh[0]; __syncthreads();

    v = g_lc_r[t];
    sh[t] = v; __syncthreads();
    #pragma unroll
    for (int o = 512; o; o >>= 1) { if (t < o) sh[t] += sh[t + o]; __syncthreads(); }
    float cr = sh[0];

    if (t == 0) {
        out[0] = sf / fmaxf(cf, 1.f);
        out[1] = sr / fmaxf(cr, 1.f);
    }
}

// ---------------- host launcher (graph-capturable, allocation-free) ----------------
extern "C" void kernel_launch(void* const* d_in, const int* in_sizes, int n_in,
                              void* d_out, int out_size) {
    (void)in_sizes; (void)n_in; (void)out_size;
    const float* f_fti = (const float*)d_in[0];
    const float* e_rcl = (const float*)d_in[1];
    const int*   tlab  = (const int*)d_in[2];
    const int*   nlab  = (const int*)d_in[3];
    const float* pf    = (const float*)d_in[4];
    const float* pr    = (const float*)d_in[5];
    float* out = (float*)d_out;

    cudaFuncSetAttribute(k_loss_tc, cudaFuncAttributeMaxDynamicSharedMemorySize, SMEM_LOSS);

    k_histp<<<2 * HB, 256>>>(tlab, nlab);
    k_scan<<<1, 512>>>();
    k_scatter2<<<(NB + NR) / 256, 256>>>(tlab, nlab);
    k_classsum2<<<CF + CR, 256>>>(f_fti, e_rcl);
    k_proto2<<<CF + CR, 256>>>(pf, pr);
    k_loss_tc<<<NR / 128 + NB / 128, 256, SMEM_LOSS>>>(tlab, nlab);
    k_final<<<1, 1024>>>(out);
}

// round 15
// speedup vs baseline: 6.8791x; 1.1789x over previous
#include <cuda_runtime.h>
#include <cuda_bf16.h>
#include <math.h>
#include <stdint.h>

#define D   256
#define NB  65536
#define NR  131072
#define CF  128
#define CR  512
#define HB  64     // hist blocks per branch
#define SEG 4      // classsum segments per class
#define EPSN  1e-12f
// (1/T) * log2(e)
#define SC2 4.8089834696296117f
#define LN2 0.6931471805599453f

// ---------------- scratch (static device globals; no runtime alloc) ----------------
__device__ int   g_ph_f[HB*CF];    // per-block partial histograms (fully overwritten)
__device__ int   g_ph_r[HB*CR];
__device__ int   g_cnt_f[CF];
__device__ int   g_cnt_r[CR];
__device__ int   g_off_f[CF];
__device__ int   g_off_r[CR];
__device__ int   g_cur_f[CF];
__device__ int   g_cur_r[CR];
__device__ int   g_srt_f[NB];
__device__ int   g_srt_r[NR];
__device__ float g_sum_f[SEG*CF*D];   // per-segment partial class sums
__device__ float g_sum_r[SEG*CR*D];
__device__ int8_t g_xq_f[NB*D];    // quantized features (written by classsum)
__device__ int8_t g_xq_r[NR*D];
__device__ float  g_xs_f[NB];      // fused per-row scale SC2*inv*mx/127
__device__ float  g_xs_r[NR];
__device__ int8_t g_pbq_f[CF*D];   // updated prototypes, int8
__device__ int8_t g_pbq_r[CR*D];
__device__ float  g_pbs_f[CF];     // per-class dequant scale (max/127)
__device__ float  g_pbs_r[CR];
__device__ float g_ls_f[NB/128];
__device__ float g_lc_f[NB/128];
__device__ float g_ls_r[NR/128];
__device__ float g_lc_r[NR/128];

__device__ __forceinline__ uint32_t smem_u32(const void* p) {
    uint32_t a;
    asm("{ .reg .u64 t; cvta.to.shared.u64 t, %1; cvt.u32.u64 %0, t; }" : "=r"(a) : "l"(p));
    return a;
}
__device__ __forceinline__ float ex2f_fast(float x) {
    float r; asm("ex2.approx.f32 %0, %1;" : "=f"(r) : "f"(x)); return r;
}
__device__ __forceinline__ float lg2f_fast(float x) {
    float r; asm("lg2.approx.f32 %0, %1;" : "=f"(r) : "f"(x)); return r;
}

#define LDSM_X4(r, addr) \
    asm volatile("ldmatrix.sync.aligned.m8n8.x4.shared.b16 {%0,%1,%2,%3}, [%4];" \
        : "=r"((r)[0]), "=r"((r)[1]), "=r"((r)[2]), "=r"((r)[3]) : "r"(addr))

__device__ __forceinline__ void mma_s8(int* c, const uint32_t* a, const uint32_t* b) {
    asm volatile(
        "mma.sync.aligned.m16n8k32.row.col.s32.s8.s8.s32 "
        "{%0,%1,%2,%3}, {%4,%5,%6,%7}, {%8,%9}, {%0,%1,%2,%3};"
        : "+r"(c[0]), "+r"(c[1]), "+r"(c[2]), "+r"(c[3])
        : "r"(a[0]), "r"(a[1]), "r"(a[2]), "r"(a[3]), "r"(b[0]), "r"(b[1]));
}

#define CP_COMMIT() asm volatile("cp.async.commit_group;" ::: "memory")
#define CP_WAIT0()  asm volatile("cp.async.wait_group 0;" ::: "memory")

// ---------------- partial histograms: no global atomics, nothing to zero ----------------
__global__ __launch_bounds__(256) void k_histp(
    const int* __restrict__ tlab, const int* __restrict__ nlab)
{
    __shared__ int sh[CR];
    bool fti = blockIdx.x < HB;
    const int* lab = fti ? tlab : nlab;
    int n = fti ? NB : NR;
    int C = fti ? CF : CR;
    int b = fti ? blockIdx.x : blockIdx.x - HB;
    int tid = threadIdx.x;
    for (int i = tid; i < C; i += 256) sh[i] = 0;
    __syncthreads();
    for (int i = b * 256 + tid; i < n; i += HB * 256) {
        int l = lab[i];
        if (l >= 0) atomicAdd(&sh[l], 1);
    }
    __syncthreads();
    int* dst = fti ? (g_ph_f + b * CF) : (g_ph_r + b * CR);
    for (int i = tid; i < C; i += 256) dst[i] = sh[i];
}

// ---------------- sum partials + exclusive scan (1 block) ----------------
__global__ void k_scan() {
    __shared__ int sh[CR];
    int t = threadIdx.x;
    int myc_f = 0, myc_r = 0;
    if (t < CF) {
        int s = 0;
        #pragma unroll 8
        for (int j = 0; j < HB; j++) s += g_ph_f[j * CF + t];
        myc_f = s; g_cnt_f[t] = s; sh[t] = s;
    }
    __syncthreads();
    for (int o = 1; o < CF; o <<= 1) {
        int v = (t < CF && t >= o) ? sh[t - o] : 0;
        __syncthreads();
        if (t < CF) sh[t] += v;
        __syncthreads();
    }
    if (t < CF) { int e = sh[t] - myc_f; g_off_f[t] = e; g_cur_f[t] = e; }
    __syncthreads();
    if (t < CR) {
        int s = 0;
        #pragma unroll 8
        for (int j = 0; j < HB; j++) s += g_ph_r[j * CR + t];
        myc_r = s; g_cnt_r[t] = s; sh[t] = s;
    }
    __syncthreads();
    for (int o = 1; o < CR; o <<= 1) {
        int v = (t < CR && t >= o) ? sh[t - o] : 0;
        __syncthreads();
        if (t < CR) sh[t] += v;
        __syncthreads();
    }
    if (t < CR) { int e = sh[t] - myc_r; g_off_r[t] = e; g_cur_r[t] = e; }
}

// ---------------- warp-aggregated scatter ----------------
__global__ void k_scatter2(const int* __restrict__ tlab, const int* __restrict__ nlab) {
    int i = blockIdx.x * blockDim.x + threadIdx.x;
    int lane = threadIdx.x & 31;
    int idx, l;
    int* cur;
    int* srt;
    if (i < NB) { idx = i;      l = tlab[idx]; cur = g_cur_f; srt = g_srt_f; }
    else        { idx = i - NB; l = nlab[idx]; cur = g_cur_r; srt = g_srt_r; }
    if (l >= 0) {
        unsigned am   = __activemask();
        unsigned mask = __match_any_sync(am, l);
        int leader = __ffs(mask) - 1;
        int rank   = __popc(mask & ((1u << lane) - 1));
        int base = 0;
        if (lane == leader) base = atomicAdd(&cur[l], __popc(mask));
        base = __shfl_sync(mask, base, leader);
        srt[base + rank] = idx;
    }
}

// ---------------- segmented classsum + X int8 quantization ----------------
// Grid SEG*(CF+CR). Block (seg, class): sums its quarter of the class's rows
// into g_sum[seg]; 2-row unroll keeps two loads + two shfl chains in flight.
// Lane holds floats [lane*4,+4) and [128+lane*4,+4) -> orow[lane], orow[32+lane].
__global__ __launch_bounds__(256) void k_classsum2(
    const float* __restrict__ Xf, const float* __restrict__ Xr)
{
    __shared__ float sh[8][256];
    int bi  = blockIdx.x;
    int seg = bi & (SEG - 1);
    int cc  = bi >> 2;
    bool fti = cc < CF;
    int c = fti ? cc : cc - CF;
    int C = fti ? CF : CR;
    const float* x   = fti ? Xf : Xr;
    const int*   srt = fti ? g_srt_f : g_srt_r;
    int s0 = fti ? g_off_f[c] : g_off_r[c];
    int n  = fti ? g_cnt_f[c] : g_cnt_r[c];
    float* sums = (fti ? g_sum_f : g_sum_r) + ((size_t)seg * C + c) * D;
    int8_t* xq  = fti ? g_xq_f : g_xq_r;
    float*  xs  = fti ? g_xs_f : g_xs_r;

    int a = (n * seg) / SEG;
    int b = (n * (seg + 1)) / SEG;
    int m = b - a;
    const int* seg_srt = srt + s0 + a;

    int tid = threadIdx.x, w = tid >> 5, lane = tid & 31;
    float a0 = 0.f, a1 = 0.f, a2 = 0.f, a3 = 0.f;
    float b0 = 0.f, b1 = 0.f, b2 = 0.f, b3 = 0.f;

    int i = w;
    for (; i + 8 < m; i += 16) {
        int idx1 = seg_srt[i];
        int idx2 = seg_srt[i + 8];
        const float4* r1 = (const float4*)(x + (size_t)idx1 * D);
        const float4* r2 = (const float4*)(x + (size_t)idx2 * D);
        float4 fa1 = r1[lane], fb1 = r1[32 + lane];
        float4 fa2 = r2[lane], fb2 = r2[32 + lane];
        float ss1 = fa1.x*fa1.x + fa1.y*fa1.y + fa1.z*fa1.z + fa1.w*fa1.w
                  + fb1.x*fb1.x + fb1.y*fb1.y + fb1.z*fb1.z + fb1.w*fb1.w;
        float ss2 = fa2.x*fa2.x + fa2.y*fa2.y + fa2.z*fa2.z + fa2.w*fa2.w
                  + fb2.x*fb2.x + fb2.y*fb2.y + fb2.z*fb2.z + fb2.w*fb2.w;
        float mx1 = fmaxf(fmaxf(fmaxf(fabsf(fa1.x), fabsf(fa1.y)), fmaxf(fabsf(fa1.z), fabsf(fa1.w))),
                          fmaxf(fmaxf(fabsf(fb1.x), fabsf(fb1.y)), fmaxf(fabsf(fb1.z), fabsf(fb1.w))));
        float mx2 = fmaxf(fmaxf(fmaxf(fabsf(fa2.x), fabsf(fa2.y)), fmaxf(fabsf(fa2.z), fabsf(fa2.w))),
                          fmaxf(fmaxf(fabsf(fb2.x), fabsf(fb2.y)), fmaxf(fabsf(fb2.z), fabsf(fb2.w))));
        #pragma unroll
        for (int o = 16; o; o >>= 1) {
            ss1 += __shfl_xor_sync(0xffffffffu, ss1, o);
            ss2 += __shfl_xor_sync(0xffffffffu, ss2, o);
            mx1  = fmaxf(mx1, __shfl_xor_sync(0xffffffffu, mx1, o));
            mx2  = fmaxf(mx2, __shfl_xor_sync(0xffffffffu, mx2, o));
        }
        mx1 = fmaxf(mx1, 1e-30f); mx2 = fmaxf(mx2, 1e-30f);
        float inv1 = 1.0f / fmaxf(sqrtf(ss1), EPSN);
        float inv2 = 1.0f / fmaxf(sqrtf(ss2), EPSN);
        float qs1 = 127.f / mx1, qs2 = 127.f / mx2;
        {
            int q0 = __float2int_rn(fa1.x * qs1), q1 = __float2int_rn(fa1.y * qs1);
            int q2 = __float2int_rn(fa1.z * qs1), q3 = __float2int_rn(fa1.w * qs1);
            int q4 = __float2int_rn(fb1.x * qs1), q5 = __float2int_rn(fb1.y * qs1);
            int q6 = __float2int_rn(fb1.z * qs1), q7 = __float2int_rn(fb1.w * qs1);
            uint32_t p0 = (q0 & 0xFF) | ((q1 & 0xFF) << 8) | ((q2 & 0xFF) << 16) | ((q3 & 0xFF) << 24);
            uint32_t p1 = (q4 & 0xFF) | ((q5 & 0xFF) << 8) | ((q6 & 0xFF) << 16) | ((q7 & 0xFF) << 24);
            uint32_t* orow = (uint32_t*)(xq + (size_t)idx1 * D);
            orow[lane] = p0; orow[32 + lane] = p1;
            if (lane == 0) xs[idx1] = SC2 * inv1 * mx1 * (1.f / 127.f);
        }
        {
            int q0 = __float2int_rn(fa2.x * qs2), q1 = __float2int_rn(fa2.y * qs2);
            int q2 = __float2int_rn(fa2.z * qs2), q3 = __float2int_rn(fa2.w * qs2);
            int q4 = __float2int_rn(fb2.x * qs2), q5 = __float2int_rn(fb2.y * qs2);
            int q6 = __float2int_rn(fb2.z * qs2), q7 = __float2int_rn(fb2.w * qs2);
            uint32_t p0 = (q0 & 0xFF) | ((q1 & 0xFF) << 8) | ((q2 & 0xFF) << 16) | ((q3 & 0xFF) << 24);
            uint32_t p1 = (q4 & 0xFF) | ((q5 & 0xFF) << 8) | ((q6 & 0xFF) << 16) | ((q7 & 0xFF) << 24);
            uint32_t* orow = (uint32_t*)(xq + (size_t)idx2 * D);
            orow[lane] = p0; orow[32 + lane] = p1;
            if (lane == 0) xs[idx2] = SC2 * inv2 * mx2 * (1.f / 127.f);
        }
        a0 += fa1.x * inv1 + fa2.x * inv2; a1 += fa1.y * inv1 + fa2.y * inv2;
        a2 += fa1.z * inv1 + fa2.z * inv2; a3 += fa1.w * inv1 + fa2.w * inv2;
        b0 += fb1.x * inv1 + fb2.x * inv2; b1 += fb1.y * inv1 + fb2.y * inv2;
        b2 += fb1.z * inv1 + fb2.z * inv2; b3 += fb1.w * inv1 + fb2.w * inv2;
    }
    for (; i < m; i += 8) {
        int idx = seg_srt[i];
        const float4* row = (const float4*)(x + (size_t)idx * D);
        float4 fa = row[lane];
        float4 fb = row[32 + lane];
        float ss = fa.x*fa.x + fa.y*fa.y + fa.z*fa.z + fa.w*fa.w
                 + fb.x*fb.x + fb.y*fb.y + fb.z*fb.z + fb.w*fb.w;
        float mx = fmaxf(fmaxf(fmaxf(fabsf(fa.x), fabsf(fa.y)), fmaxf(fabsf(fa.z), fabsf(fa.w))),
                         fmaxf(fmaxf(fabsf(fb.x), fabsf(fb.y)), fmaxf(fabsf(fb.z), fabsf(fb.w))));
        #pragma unroll
        for (int o = 16; o; o >>= 1) {
            ss += __shfl_xor_sync(0xffffffffu, ss, o);
            mx  = fmaxf(mx, __shfl_xor_sync(0xffffffffu, mx, o));
        }
        mx = fmaxf(mx, 1e-30f);
        float inv = 1.0f / fmaxf(sqrtf(ss), EPSN);
        float qs = 127.f / mx;
        int q0 = __float2int_rn(fa.x * qs), q1 = __float2int_rn(fa.y * qs);
        int q2 = __float2int_rn(fa.z * qs), q3 = __float2int_rn(fa.w * qs);
        int q4 = __float2int_rn(fb.x * qs), q5 = __float2int_rn(fb.y * qs);
        int q6 = __float2int_rn(fb.z * qs), q7 = __float2int_rn(fb.w * qs);
        uint32_t p0 = (q0 & 0xFF) | ((q1 & 0xFF) << 8) | ((q2 & 0xFF) << 16) | ((q3 & 0xFF) << 24);
        uint32_t p1 = (q4 & 0xFF) | ((q5 & 0xFF) << 8) | ((q6 & 0xFF) << 16) | ((q7 & 0xFF) << 24);
        uint32_t* orow = (uint32_t*)(xq + (size_t)idx * D);
        orow[lane] = p0; orow[32 + lane] = p1;
        if (lane == 0) xs[idx] = SC2 * inv * mx * (1.f / 127.f);
        a0 += fa.x * inv; a1 += fa.y * inv; a2 += fa.z * inv; a3 += fa.w * inv;
        b0 += fb.x * inv; b1 += fb.y * inv; b2 += fb.z * inv; b3 += fb.w * inv;
    }
    sh[w][lane * 4 + 0] = a0; sh[w][lane * 4 + 1] = a1;
    sh[w][lane * 4 + 2] = a2; sh[w][lane * 4 + 3] = a3;
    sh[w][128 + lane * 4 + 0] = b0; sh[w][128 + lane * 4 + 1] = b1;
    sh[w][128 + lane * 4 + 2] = b2; sh[w][128 + lane * 4 + 3] = b3;
    __syncthreads();
    float s = 0.f;
    #pragma unroll
    for (int ww = 0; ww < 8; ww++) s += sh[ww][tid];
    sums[tid] = s;
}

// ---------------- fused prototype EMA update -> int8 + per-class scale ----------------
__global__ __launch_bounds__(256) void k_proto2(
    const float* __restrict__ pf, const float* __restrict__ pr)
{
    __shared__ float sh[256];
    bool fti = blockIdx.x < CF;
    int c = fti ? blockIdx.x : blockIdx.x - CF;
    int C = fti ? CF : CR;
    int n = fti ? g_cnt_f[c] : g_cnt_r[c];
    const float* sums = (fti ? g_sum_f : g_sum_r);
    const float* pin  = (fti ? pf : pr) + c * D;
    int8_t* pout = (fti ? g_pbq_f : g_pbq_r) + c * D;
    float*  psc  = fti ? g_pbs_f : g_pbs_r;

    int t = threadIdx.x;
    float acc = 0.f;
    #pragma unroll
    for (int seg = 0; seg < SEG; seg++)
        acc += sums[((size_t)seg * C + c) * D + t];
    float mv = acc / fmaxf((float)n, 1.f);
    sh[t] = mv * mv;
    __syncthreads();
    #pragma unroll
    for (int o = 128; o; o >>= 1) { if (t < o) sh[t] += sh[t + o]; __syncthreads(); }
    float nm = fmaxf(sqrtf(sh[0]), EPSN);
    __syncthreads();
    mv = mv / nm;
    float p = pin[t];
    float q = 0.5f * p + 0.5f * mv;
    sh[t] = q * q;
    __syncthreads();
    #pragma unroll
    for (int o = 128; o; o >>= 1) { if (t < o) sh[t] += sh[t + o]; __syncthreads(); }
    float nq = fmaxf(sqrtf(sh[0]), EPSN);
    float val = (n > 0) ? q / nq : p;
    __syncthreads();
    sh[t] = fabsf(val);
    __syncthreads();
    #pragma unroll
    for (int o = 128; o; o >>= 1) { if (t < o) sh[t] = fmaxf(sh[t], sh[t + o]); __syncthreads(); }
    float m = fmaxf(sh[0], 1e-30f);
    int qv = __float2int_rn(val * (127.f / m));
    qv = max(-127, min(127, qv));
    pout[t] = (int8_t)qv;
    if (t == 0) psc[c] = m * (1.f / 127.f);
}

// ---------------- int8 mma.sync fused GEMM + softmax CE ----------------
// smem: 0 lab | 512 scale | 1024 rs | 2048 tg | 3072 red | 3200 scb[512]
//       5376 A(34816) | 40192 B0(34816) | 75008 B1(34816) -> 109824 (2 CTA/SM)
#define A_OFF   5376
#define B0_OFF  40192
#define BBUF    34816
#define SMEM_LOSS 109824
#define NBLK_R (NR/128)

__device__ __forceinline__ void prefetch_T(uint32_t sbu, uint32_t dstOff,
                                           const int8_t* __restrict__ P,
                                           int r0, int tid) {
    #pragma unroll
    for (int i = 0; i < 8; i++) {
        int ch = tid + i * 256;
        int r  = ch >> 4;
        int c16 = (ch & 15) * 16;
        uint32_t dst = sbu + dstOff + (uint32_t)(r * 272 + c16);
        const void* src = P + (size_t)(r0 + r) * D + c16;
        asm volatile("cp.async.cg.shared.global [%0], [%1], 16;" :: "r"(dst), "l"(src));
    }
}

__global__ __launch_bounds__(256, 2)
void k_loss_tc(const int* __restrict__ tlab, const int* __restrict__ nlab)
{
    extern __shared__ char smem[];
    int*   lab_sm   = (int*)(smem + 0);
    float* scale_sm = (float*)(smem + 512);
    float* rs_sm    = (float*)(smem + 1024);
    float* tg_sm    = (float*)(smem + 2048);
    float* red_s    = (float*)(smem + 3072);
    float* red_c    = (float*)(smem + 3104);
    float* scb_sm   = (float*)(smem + 3200);

    const bool fti = blockIdx.x >= NBLK_R;
    const int  bid = fti ? blockIdx.x - NBLK_R : blockIdx.x;
    const int8_t* Xq = fti ? g_xq_f : g_xq_r;
    const float*  Xs = fti ? g_xs_f : g_xs_r;
    const int8_t* Pq = fti ? g_pbq_f : g_pbq_r;
    const float*  Ps = fti ? g_pbs_f : g_pbs_r;
    const int* lab = fti ? tlab : nlab;
    float* lsum = fti ? g_ls_f : g_ls_r;
    float* lcnt = fti ? g_lc_f : g_lc_r;
    const int NCH = fti ? (CF / 128) : (CR / 128);

    const int tid  = threadIdx.x;
    const int wid  = tid >> 5;
    const int lane = tid & 31;
    const int wr   = wid & 3;
    const int wc   = wid >> 2;
    const int row0 = bid * 128;
    const uint32_t sbu = smem_u32(smem);

    prefetch_T(sbu, A_OFF, Xq, row0, tid);
    prefetch_T(sbu, B0_OFF, Pq, 0, tid);
    CP_COMMIT();
    if (tid < 128) {
        lab_sm[tid]   = lab[row0 + tid];
        scale_sm[tid] = Xs[row0 + tid];
    }
    for (int i = tid; i < NCH * 128; i += 256) scb_sm[i] = Ps[i];
    CP_WAIT0();
    __syncthreads();

    int lb4[4]; float sc4[4];
    #pragma unroll
    for (int mt = 0; mt < 2; mt++)
        #pragma unroll
        for (int h = 0; h < 2; h++) {
            int r = wr * 32 + mt * 16 + (lane >> 2) + h * 8;
            lb4[mt * 2 + h] = lab_sm[r];
            sc4[mt * 2 + h] = scale_sm[r];
        }

    const uint32_t aBase = sbu + A_OFF
        + (uint32_t)(wr * 32 + (lane & 15)) * 272 + (uint32_t)(lane >> 4) * 16;
    const uint32_t bB0 = sbu + B0_OFF
        + (uint32_t)(wc * 64 + (lane & 7) + ((lane >> 4) & 1) * 8) * 272
        + (uint32_t)((lane >> 3) & 1) * 16;

    float ssum[4] = {0.f, 0.f, 0.f, 0.f};
    float tgt[4]  = {0.f, 0.f, 0.f, 0.f};

    for (int c = 0; c < NCH; c++) {
        if (c) { CP_WAIT0(); __syncthreads(); }
        if (c + 1 < NCH) {
            prefetch_T(sbu, B0_OFF + (uint32_t)((c + 1) & 1) * BBUF, Pq, (c + 1) * 128, tid);
            CP_COMMIT();
        }
        const uint32_t bBase = bB0 + (uint32_t)(c & 1) * BBUF;

        int acc[2][8][4];
        #pragma unroll
        for (int mt = 0; mt < 2; mt++)
            #pragma unroll
            for (int nt = 0; nt < 8; nt++)
                #pragma unroll
                for (int e = 0; e < 4; e++) acc[mt][nt][e] = 0;

        #pragma unroll
        for (int k = 0; k < 8; k++) {
            uint32_t aoff = (uint32_t)k * 32;
            uint32_t ah0[4], ah1[4];
            LDSM_X4(ah0, aBase + aoff);
            LDSM_X4(ah1, aBase + 4352 + aoff);
            #pragma unroll
            for (int ntp = 0; ntp < 4; ntp++) {
                uint32_t bh[4];
                LDSM_X4(bh, bBase + (uint32_t)ntp * 4352 + aoff);
                mma_s8(acc[0][ntp*2],   ah0, bh);
                mma_s8(acc[1][ntp*2],   ah1, bh);
                mma_s8(acc[0][ntp*2+1], ah0, bh + 2);
                mma_s8(acc[1][ntp*2+1], ah1, bh + 2);
            }
        }

        int c0 = c * 128;
        #pragma unroll
        for (int nt = 0; nt < 8; nt++) {
            int colb = c0 + wc * 64 + nt * 8 + (lane & 3) * 2;
            float sb0 = scb_sm[colb];
            float sb1 = scb_sm[colb + 1];
            #pragma unroll
            for (int mt = 0; mt < 2; mt++) {
                float l0 = __int2float_rn(acc[mt][nt][0]) * sc4[mt*2]   * sb0;
                float l1 = __int2float_rn(acc[mt][nt][1]) * sc4[mt*2]   * sb1;
                float l2 = __int2float_rn(acc[mt][nt][2]) * sc4[mt*2+1] * sb0;
                float l3 = __int2float_rn(acc[mt][nt][3]) * sc4[mt*2+1] * sb1;
                ssum[mt*2]   += ex2f_fast(l0) + ex2f_fast(l1);
                ssum[mt*2+1] += ex2f_fast(l2) + ex2f_fast(l3);
                if (lb4[mt*2]   == colb)     tgt[mt*2]   = l0;
                if (lb4[mt*2]   == colb + 1) tgt[mt*2]   = l1;
                if (lb4[mt*2+1] == colb)     tgt[mt*2+1] = l2;
                if (lb4[mt*2+1] == colb + 1) tgt[mt*2+1] = l3;
            }
        }
    }

    #pragma unroll
    for (int i = 0; i < 4; i++) {
        ssum[i] += __shfl_xor_sync(0xffffffffu, ssum[i], 1);
        ssum[i] += __shfl_xor_sync(0xffffffffu, ssum[i], 2);
        tgt[i]  += __shfl_xor_sync(0xffffffffu, tgt[i], 1);
        tgt[i]  += __shfl_xor_sync(0xffffffffu, tgt[i], 2);
    }
    if ((lane & 3) == 0) {
        #pragma unroll
        for (int i = 0; i < 4; i++) {
            int r = wr * 32 + (i >> 1) * 16 + (lane >> 2) + (i & 1) * 8;
            rs_sm[r * 2 + wc] = ssum[i];
            tg_sm[r * 2 + wc] = tgt[i];
        }
    }
    __syncthreads();

    float v = 0.f, cn = 0.f;
    if (tid < 128) {
        int lb = lab_sm[tid];
        if (lb >= 0) {
            float S  = rs_sm[tid * 2] + rs_sm[tid * 2 + 1];
            float T2 = tg_sm[tid * 2] + tg_sm[tid * 2 + 1];
            v  = LN2 * (lg2f_fast(S) - T2);
            cn = 1.f;
        }
    }
    #pragma unroll
    for (int o = 16; o; o >>= 1) {
        v  += __shfl_xor_sync(0xffffffffu, v, o);
        cn += __shfl_xor_sync(0xffffffffu, cn, o);
    }
    if (lane == 0) { red_s[wid] = v; red_c[wid] = cn; }
    __syncthreads();
    if (tid == 0) {
        lsum[bid] = red_s[0] + red_s[1] + red_s[2] + red_s[3];
        lcnt[bid] = red_c[0] + red_c[1] + red_c[2] + red_c[3];
    }
}

// ---------------- final reduction of per-block partials ----------------
__global__ void k_final(float* __restrict__ out) {
    __shared__ float sh[1024];
    int t = threadIdx.x;
    float v;

    v = (t < NB / 128) ? g_ls_f[t] : 0.f;
    sh[t] = v; __syncthreads();
    #pragma unroll
    for (int o = 512; o; o >>= 1) { if (t < o) sh[t] += sh[t + o]; __syncthreads(); }
    float sf = sh[0]; __syncthreads();

    v = (t < NB / 128) ? g_lc_f[t] : 0.f;
    sh[t] = v; __syncthreads();
    #pragma unroll
    for (int o = 512; o; o >>= 1) { if (t < o) sh[t] += sh[t + o]; __syncthreads(); }
    float cf = sh[0]; __syncthreads();

    v = g_ls_r[t];
    sh[t] = v; __syncthreads();
    #pragma unroll
    for (int o = 512; o; o >>= 1) { if (t < o) sh[t] += sh[t + o]; __syncthreads(); }
    float sr = sh[0]; __syncthreads();

    v = g_lc_r[t];
    sh[t] = v; __syncthreads();
    #pragma unroll
    for (int o = 512; o; o >>= 1) { if (t < o) sh[t] += sh[t + o]; __syncthreads(); }
    float cr = sh[0];

    if (t == 0) {
        out[0] = sf / fmaxf(cf, 1.f);
        out[1] = sr / fmaxf(cr, 1.f);
    }
}

// ---------------- host launcher (graph-capturable, allocation-free) ----------------
extern "C" void kernel_launch(void* const* d_in, const int* in_sizes, int n_in,
                              void* d_out, int out_size) {
    (void)in_sizes; (void)n_in; (void)out_size;
    const float* f_fti = (const float*)d_in[0];
    const float* e_rcl = (const float*)d_in[1];
    const int*   tlab  = (const int*)d_in[2];
    const int*   nlab  = (const int*)d_in[3];
    const float* pf    = (const float*)d_in[4];
    const float* pr    = (const float*)d_in[5];
    float* out = (float*)d_out;

    cudaFuncSetAttribute(k_loss_tc, cudaFuncAttributeMaxDynamicSharedMemorySize, SMEM_LOSS);

    k_histp<<<2 * HB, 256>>>(tlab, nlab);
    k_scan<<<1, 512>>>();
    k_scatter2<<<(NB + NR) / 256, 256>>>(tlab, nlab);
    k_classsum2<<<SEG * (CF + CR), 256>>>(f_fti, e_rcl);
    k_proto2<<<CF + CR, 256>>>(pf, pr);
    k_loss_tc<<<NR / 128 + NB / 128, 256, SMEM_LOSS>>>(tlab, nlab);
    k_final<<<1, 1024>>>(out);
}